// round 12
// baseline (speedup 1.0000x reference)
#include <cuda_runtime.h>
#include <cuda_fp16.h>

// ---------------- problem constants ----------------
#define Bb 4
#define NN 1024
#define DIMV 1024
#define HH 16
#define DHd 64
#define VOC 129            // 2*MAXREL+1
#define MAXREL 64
#define TOPKv 256
#define BHH (Bb*HH)        // 64
#define ROWS (BHH*NN)      // 65536
#define SCALEv 0.125f      // DH^-0.5

typedef unsigned long long u64;

// ---------------- device scratch (no allocs allowed) ----------------
__device__ float g_Q[ROWS*DHd];
__device__ __half g_Q16h[ROWS*DHd];
__device__ __half g_Q16l[ROWS*DHd];
__device__ __half g_K16h[ROWS*DHd];
__device__ __half g_K16l[ROWS*DHd];
__device__ __half g_V16[ROWS*DHd];
__device__ float g_S[(size_t)ROWS*NN];        // 256 MB scores
__device__ float g_QR[ROWS*VOC];              // q @ rel_k_emb^T
__device__ float g_CW[ROWS*TOPKv];            // compact attn weights
__device__ int   g_CI[ROWS*TOPKv];            // compact attn column indices
__device__ float g_ARel[ROWS*DHd];            // attn @ rel_v
__device__ __half g_VA16[ROWS*DHd];
__device__ __half g_VB16[ROWS*DHd];
__device__ float g_Res[ROWS*DHd];

// ---------------- packed f32x2 helpers ----------------
__device__ __forceinline__ void ffma2(u64 &d, u64 a, u64 b) {
    asm("fma.rn.f32x2 %0, %1, %2, %0;" : "+l"(d) : "l"(a), "l"(b));
}
__device__ __forceinline__ u64 dup2(float x) {
    u64 r; asm("mov.b64 %0, {%1, %1};" : "=l"(r) : "f"(x)); return r;
}
__device__ __forceinline__ float2 unpack2(u64 v) {
    float2 f; asm("mov.b64 {%0, %1}, %2;" : "=f"(f.x), "=f"(f.y) : "l"(v)); return f;
}
__device__ __forceinline__ unsigned smem_u32(const void* p) {
    unsigned a;
    asm("{ .reg .u64 t; cvta.to.shared.u64 t, %1; cvt.u32.u64 %0, t; }" : "=r"(a) : "l"(p));
    return a;
}
// split f -> hi fp16 + lo fp16
__device__ __forceinline__ void split16(float f, __half &h, __half &l) {
    h = __float2half_rn(f);
    l = __float2half_rn(f - __half2float(h));
}

// =====================================================================
// Kernel 1: qkv = x @ Wqkv^T + bqkv -> Q (fp32 + fp16 hi/lo),
// K (fp16 hi/lo), V (fp16). 128x128 tile, BK=16, reg db, FFMA2.
// =====================================================================
__global__ __launch_bounds__(256) void k_gemm_qkv(const float* __restrict__ X,
                                                  const float* __restrict__ W,
                                                  const float* __restrict__ bias) {
    __shared__ float As[16][128];
    __shared__ float Bs[16][128];
    int tid = threadIdx.x;
    int tx = tid & 15, ty = tid >> 4;
    int m0 = blockIdx.y * 128, c0 = blockIdx.x * 128;
    u64 acc2[8][4] = {};

    int lr0 = tid >> 2, lk = (tid & 3) * 4;
    int lr1 = lr0 + 64;
    const float* pa0 = &X[(size_t)(m0 + lr0) * DIMV + lk];
    const float* pa1 = &X[(size_t)(m0 + lr1) * DIMV + lk];
    const float* pb0 = &W[(size_t)(c0 + lr0) * DIMV + lk];
    const float* pb1 = &W[(size_t)(c0 + lr1) * DIMV + lk];

    float4 ra0 = *(const float4*)pa0;
    float4 ra1 = *(const float4*)pa1;
    float4 rb0 = *(const float4*)pb0;
    float4 rb1 = *(const float4*)pb1;

    for (int k0 = 0; k0 < DIMV; k0 += 16) {
        As[lk+0][lr0] = ra0.x; As[lk+1][lr0] = ra0.y; As[lk+2][lr0] = ra0.z; As[lk+3][lr0] = ra0.w;
        As[lk+0][lr1] = ra1.x; As[lk+1][lr1] = ra1.y; As[lk+2][lr1] = ra1.z; As[lk+3][lr1] = ra1.w;
        Bs[lk+0][lr0] = rb0.x; Bs[lk+1][lr0] = rb0.y; Bs[lk+2][lr0] = rb0.z; Bs[lk+3][lr0] = rb0.w;
        Bs[lk+0][lr1] = rb1.x; Bs[lk+1][lr1] = rb1.y; Bs[lk+2][lr1] = rb1.z; Bs[lk+3][lr1] = rb1.w;
        __syncthreads();
        if (k0 + 16 < DIMV) {
            ra0 = *(const float4*)(pa0 + k0 + 16);
            ra1 = *(const float4*)(pa1 + k0 + 16);
            rb0 = *(const float4*)(pb0 + k0 + 16);
            rb1 = *(const float4*)(pb1 + k0 + 16);
        }
        #pragma unroll
        for (int k = 0; k < 16; k++) {
            float4 a0 = *(const float4*)&As[k][ty * 4];
            float4 a1 = *(const float4*)&As[k][ty * 4 + 64];
            ulonglong2 b0 = *(const ulonglong2*)&Bs[k][tx * 4];
            ulonglong2 b1 = *(const ulonglong2*)&Bs[k][tx * 4 + 64];
            u64 ad[8];
            ad[0]=dup2(a0.x); ad[1]=dup2(a0.y); ad[2]=dup2(a0.z); ad[3]=dup2(a0.w);
            ad[4]=dup2(a1.x); ad[5]=dup2(a1.y); ad[6]=dup2(a1.z); ad[7]=dup2(a1.w);
            #pragma unroll
            for (int i = 0; i < 8; i++) {
                ffma2(acc2[i][0], ad[i], b0.x);
                ffma2(acc2[i][1], ad[i], b0.y);
                ffma2(acc2[i][2], ad[i], b1.x);
                ffma2(acc2[i][3], ad[i], b1.y);
            }
        }
        __syncthreads();
    }
    #pragma unroll
    for (int ih = 0; ih < 2; ih++) {
        #pragma unroll
        for (int i = 0; i < 4; i++) {
            int m = m0 + ih * 64 + ty * 4 + i;
            int b = m >> 10, n = m & 1023;
            #pragma unroll
            for (int jh = 0; jh < 2; jh++) {
                int c = c0 + jh * 64 + tx * 4;
                float2 lo = unpack2(acc2[ih*4+i][jh*2+0]);
                float2 hi = unpack2(acc2[ih*4+i][jh*2+1]);
                float4 v;
                v.x = lo.x + bias[c+0];
                v.y = lo.y + bias[c+1];
                v.z = hi.x + bias[c+2];
                v.w = hi.y + bias[c+3];
                int part = c >> 10;
                int hc = c & 1023;
                int h = hc >> 6, dh = hc & 63;
                size_t idx = ((size_t)((b * HH + h) * NN + n)) * DHd + dh;
                if (part == 2) {
                    __half2 h01 = __floats2half2_rn(v.x, v.y);
                    __half2 h23 = __floats2half2_rn(v.z, v.w);
                    uint2 pk;
                    pk.x = *(unsigned*)&h01;
                    pk.y = *(unsigned*)&h23;
                    *(uint2*)&g_V16[idx] = pk;
                } else {
                    __half hh[4], hl[4];
                    split16(v.x, hh[0], hl[0]);
                    split16(v.y, hh[1], hl[1]);
                    split16(v.z, hh[2], hl[2]);
                    split16(v.w, hh[3], hl[3]);
                    uint2 ph = make_uint2(*(unsigned*)&hh[0], *(unsigned*)&hh[2]);
                    uint2 pl = make_uint2(*(unsigned*)&hl[0], *(unsigned*)&hl[2]);
                    if (part == 0) {
                        *(float4*)&g_Q[idx] = v;
                        *(uint2*)&g_Q16h[idx] = ph;
                        *(uint2*)&g_Q16l[idx] = pl;
                    } else {
                        *(uint2*)&g_K16h[idx] = ph;
                        *(uint2*)&g_K16l[idx] = pl;
                    }
                }
            }
        }
    }
}

// =====================================================================
// Kernel 2: QR[row][t] = Q[row] . rel_k_emb[t]  (fp32, smem-staged)
// =====================================================================
__global__ __launch_bounds__(256) void k_qr(const float* __restrict__ relk) {
    __shared__ float sQ[32][68];
    __shared__ float srk[64][132];
    int tid = threadIdx.x;
    int row0 = blockIdx.x * 32;
    for (int e = tid; e < 32 * 64; e += 256) {
        int r = e >> 6, d = e & 63;
        sQ[r][d] = g_Q[(size_t)(row0 + r) * DHd + d];
    }
    for (int e = tid; e < 64 * 132; e += 256) {
        int d = e / 132, t = e % 132;
        srk[d][t] = (t < VOC) ? relk[t * DHd + d] : 0.f;
    }
    __syncthreads();
    for (int g = tid; g < 32 * 33; g += 256) {
        int r = g / 33, tt = g % 33;
        u64 a01 = 0, a23 = 0;
        #pragma unroll 16
        for (int d = 0; d < 64; d++) {
            u64 qd = dup2(sQ[r][d]);
            ulonglong2 f = *(const ulonglong2*)&srk[d][tt * 4];
            ffma2(a01, qd, f.x);
            ffma2(a23, qd, f.y);
        }
        float2 lo = unpack2(a01), hi = unpack2(a23);
        size_t base = (size_t)(row0 + r) * VOC;
        int t0 = tt * 4;
        if (tt < 32) {
            g_QR[base + t0 + 0] = lo.x;
            g_QR[base + t0 + 1] = lo.y;
            g_QR[base + t0 + 2] = hi.x;
            g_QR[base + t0 + 3] = hi.y;
        } else {
            g_QR[base + 128] = lo.x;
        }
    }
}

// =====================================================================
// Kernel 3: S = SCALE*(Q.K^T) + QR gather via split-fp16 tensor MMA:
// acc = Qh.Kh + Qh.Kl + Ql.Kh  (fp32-accurate).
// 128x128 tile, 8 warps 4(m)x2(n), m16n8k16, dynamic smem 4 tiles.
// grid (8, 8, 64), 256 threads.
// =====================================================================
__global__ __launch_bounds__(256) void k_scores() {
    extern __shared__ __half sdyn[];
    __half (*sQh)[72] = (__half(*)[72])(sdyn);
    __half (*sQl)[72] = (__half(*)[72])(sdyn + 128 * 72);
    __half (*sKh)[72] = (__half(*)[72])(sdyn + 2 * 128 * 72);
    __half (*sKl)[72] = (__half(*)[72])(sdyn + 3 * 128 * 72);
    int tid = threadIdx.x;
    int lane = tid & 31, wid = tid >> 5;
    int warp_m = wid & 3;
    int warp_n = wid >> 2;
    int bh = blockIdx.z;
    int i0 = blockIdx.y * 128, j0 = blockIdx.x * 128;

    {
        const __half* gqh = g_Q16h + (size_t)(bh * NN + i0) * DHd;
        const __half* gql = g_Q16l + (size_t)(bh * NN + i0) * DHd;
        const __half* gkh = g_K16h + (size_t)(bh * NN + j0) * DHd;
        const __half* gkl = g_K16l + (size_t)(bh * NN + j0) * DHd;
        for (int e = tid; e < 1024; e += 256) {
            int r = e >> 3, s = (e & 7) * 8;
            *(uint4*)&sQh[r][s] = *(const uint4*)&gqh[r * DHd + s];
            *(uint4*)&sQl[r][s] = *(const uint4*)&gql[r * DHd + s];
            *(uint4*)&sKh[r][s] = *(const uint4*)&gkh[r * DHd + s];
            *(uint4*)&sKl[r][s] = *(const uint4*)&gkl[r * DHd + s];
        }
    }
    __syncthreads();

    float acc[2][8][4];
    #pragma unroll
    for (int ma = 0; ma < 2; ma++)
        #pragma unroll
        for (int na = 0; na < 8; na++)
            #pragma unroll
            for (int q = 0; q < 4; q++) acc[ma][na][q] = 0.f;

    int lm = lane >> 3;
    int lr = lane & 7;
    int aRowOff = (lm & 1) * 8 + lr;
    int aColOff = (lm >> 1) * 8;
    int bRowOff = (lm >> 1) * 8 + lr;
    int bColOff = (lm & 1) * 8;

    #pragma unroll
    for (int kk = 0; kk < 4; kk++) {
        int kbase = kk * 16;
        unsigned ah[2][4], al[2][4];
        #pragma unroll
        for (int ma = 0; ma < 2; ma++) {
            int rowq = warp_m * 32 + ma * 16 + aRowOff;
            unsigned addrh = smem_u32(&sQh[rowq][kbase + aColOff]);
            asm volatile("ldmatrix.sync.aligned.m8n8.x4.shared.b16 {%0,%1,%2,%3}, [%4];"
                         : "=r"(ah[ma][0]), "=r"(ah[ma][1]), "=r"(ah[ma][2]), "=r"(ah[ma][3])
                         : "r"(addrh));
            unsigned addrl = smem_u32(&sQl[rowq][kbase + aColOff]);
            asm volatile("ldmatrix.sync.aligned.m8n8.x4.shared.b16 {%0,%1,%2,%3}, [%4];"
                         : "=r"(al[ma][0]), "=r"(al[ma][1]), "=r"(al[ma][2]), "=r"(al[ma][3])
                         : "r"(addrl));
        }
        unsigned bh_[8][2], bl_[8][2];
        #pragma unroll
        for (int np = 0; np < 4; np++) {
            int rowk = warp_n * 64 + np * 16 + bRowOff;
            unsigned r0, r1, r2, r3;
            unsigned addrh = smem_u32(&sKh[rowk][kbase + bColOff]);
            asm volatile("ldmatrix.sync.aligned.m8n8.x4.shared.b16 {%0,%1,%2,%3}, [%4];"
                         : "=r"(r0), "=r"(r1), "=r"(r2), "=r"(r3) : "r"(addrh));
            bh_[np*2+0][0] = r0; bh_[np*2+0][1] = r1;
            bh_[np*2+1][0] = r2; bh_[np*2+1][1] = r3;
            unsigned addrl = smem_u32(&sKl[rowk][kbase + bColOff]);
            asm volatile("ldmatrix.sync.aligned.m8n8.x4.shared.b16 {%0,%1,%2,%3}, [%4];"
                         : "=r"(r0), "=r"(r1), "=r"(r2), "=r"(r3) : "r"(addrl));
            bl_[np*2+0][0] = r0; bl_[np*2+0][1] = r1;
            bl_[np*2+1][0] = r2; bl_[np*2+1][1] = r3;
        }
        #pragma unroll
        for (int ma = 0; ma < 2; ma++) {
            #pragma unroll
            for (int na = 0; na < 8; na++) {
                asm volatile(
                    "mma.sync.aligned.m16n8k16.row.col.f32.f16.f16.f32 "
                    "{%0,%1,%2,%3}, {%4,%5,%6,%7}, {%8,%9}, {%0,%1,%2,%3};"
                    : "+f"(acc[ma][na][0]), "+f"(acc[ma][na][1]),
                      "+f"(acc[ma][na][2]), "+f"(acc[ma][na][3])
                    : "r"(ah[ma][0]), "r"(ah[ma][1]), "r"(ah[ma][2]), "r"(ah[ma][3]),
                      "r"(bh_[na][0]), "r"(bh_[na][1]));
                asm volatile(
                    "mma.sync.aligned.m16n8k16.row.col.f32.f16.f16.f32 "
                    "{%0,%1,%2,%3}, {%4,%5,%6,%7}, {%8,%9}, {%0,%1,%2,%3};"
                    : "+f"(acc[ma][na][0]), "+f"(acc[ma][na][1]),
                      "+f"(acc[ma][na][2]), "+f"(acc[ma][na][3])
                    : "r"(ah[ma][0]), "r"(ah[ma][1]), "r"(ah[ma][2]), "r"(ah[ma][3]),
                      "r"(bl_[na][0]), "r"(bl_[na][1]));
                asm volatile(
                    "mma.sync.aligned.m16n8k16.row.col.f32.f16.f16.f32 "
                    "{%0,%1,%2,%3}, {%4,%5,%6,%7}, {%8,%9}, {%0,%1,%2,%3};"
                    : "+f"(acc[ma][na][0]), "+f"(acc[ma][na][1]),
                      "+f"(acc[ma][na][2]), "+f"(acc[ma][na][3])
                    : "r"(al[ma][0]), "r"(al[ma][1]), "r"(al[ma][2]), "r"(al[ma][3]),
                      "r"(bh_[na][0]), "r"(bh_[na][1]));
            }
        }
    }

    // epilogue: scale + QR gather + store
    int g = lane >> 2, tg = lane & 3;
    #pragma unroll
    for (int ma = 0; ma < 2; ma++) {
        int rowA = i0 + warp_m * 32 + ma * 16 + g;
        #pragma unroll
        for (int half = 0; half < 2; half++) {
            int ii = rowA + half * 8;
            const float* qr = &g_QR[(size_t)(bh * NN + ii) * VOC];
            size_t sbase = ((size_t)(bh * NN + ii)) * NN;
            #pragma unroll
            for (int na = 0; na < 8; na++) {
                int jj = j0 + warp_n * 64 + na * 8 + tg * 2;
                int d0 = ii - jj;
                d0 = d0 < -MAXREL ? -MAXREL : (d0 > MAXREL ? MAXREL : d0);
                int d1 = ii - (jj + 1);
                d1 = d1 < -MAXREL ? -MAXREL : (d1 > MAXREL ? MAXREL : d1);
                float2 v;
                v.x = acc[ma][na][half*2+0] * SCALEv + qr[d0 + MAXREL];
                v.y = acc[ma][na][half*2+1] * SCALEv + qr[d1 + MAXREL];
                *(float2*)&g_S[sbase + jj] = v;
            }
        }
    }
}

// float -> order-preserving uint key
__device__ __forceinline__ unsigned ftokey(float f) {
    unsigned u = __float_as_uint(f);
    return (u & 0x80000000u) ? ~u : (u | 0x80000000u);
}

// =====================================================================
// Kernel 4 (fused): radix-select exact top-256 threshold + masked softmax
// + deterministic compaction + rel_v bucket trick -> ARel.
// (proven R6 form) One block (256 threads) per score row.
// =====================================================================
__global__ __launch_bounds__(256) void k_select(const float* __restrict__ relv) {
    __shared__ float sbuf[1024];
    __shared__ int   hist[256];
    __shared__ float wredf[8];
    __shared__ float wredf2[8];
    __shared__ int   wredi[8];
    __shared__ float rbin[VOC];
    __shared__ unsigned sh_selb;
    __shared__ int      sh_rem;

    int row = blockIdx.x;
    int tid = threadIdx.x;
    int lane = tid & 31, wid = tid >> 5;
    int i = row & (NN - 1);
    const float* src = &g_S[(size_t)row * NN];

    float lv[4]; unsigned kv[4];
    #pragma unroll
    for (int r = 0; r < 4; r++) {
        int j = tid * 4 + r;
        lv[r] = src[j];
        kv[r] = ftokey(lv[r]);
    }

    // ---- row max ----
    float m = fmaxf(fmaxf(lv[0], lv[1]), fmaxf(lv[2], lv[3]));
    #pragma unroll
    for (int off = 16; off > 0; off >>= 1)
        m = fmaxf(m, __shfl_xor_sync(0xffffffffu, m, off));
    if (lane == 0) wredf[wid] = m;
    __syncthreads();
    float rmax = wredf[0];
    #pragma unroll
    for (int w = 1; w < 8; w++) rmax = fmaxf(rmax, wredf[w]);

    // ---- radix select: exact key of the 256th largest ----
    unsigned prefix = 0;
    int need = TOPKv;
    for (int round = 3; round >= 0; round--) {
        hist[tid] = 0;
        __syncthreads();
        unsigned mask = (round == 3) ? 0u : (0xFFFFFFFFu << ((round + 1) * 8));
        #pragma unroll
        for (int r = 0; r < 4; r++) {
            if ((kv[r] & mask) == prefix)
                atomicAdd(&hist[(kv[r] >> (round * 8)) & 255], 1);
        }
        __syncthreads();
        int h = hist[tid];
        int s = h;
        #pragma unroll
        for (int off = 1; off < 32; off <<= 1) {
            int v = __shfl_down_sync(0xffffffffu, s, off);
            if (lane + off < 32) s += v;
        }
        int wtot = __shfl_sync(0xffffffffu, s, 0);
        if (lane == 0) wredi[wid] = wtot;
        __syncthreads();
        int tail = 0;
        #pragma unroll
        for (int w = 0; w < 8; w++) if (w > wid) tail += wredi[w];
        int Sb = s + tail;
        int Sb1 = Sb - h;
        if (Sb >= need && Sb1 < need) { sh_selb = (unsigned)tid; sh_rem = Sb1; }
        __syncthreads();
        prefix |= sh_selb << (round * 8);
        need -= sh_rem;
        __syncthreads();
    }
    unsigned thrkey = prefix;

    // ---- masked exp + block sum ----
    float lsum = 0.f;
    #pragma unroll
    for (int r = 0; r < 4; r++) {
        int j = tid * 4 + r;
        float e;
        if (kv[r] >= thrkey) { e = __expf(lv[r] - rmax); lsum += e; }
        else e = -1.0f;
        sbuf[j] = e;
    }
    float ws = lsum;
    #pragma unroll
    for (int off = 16; off > 0; off >>= 1)
        ws += __shfl_xor_sync(0xffffffffu, ws, off);
    if (lane == 0) wredf[wid] = ws;
    __syncthreads();
    float tot = 0.f;
    #pragma unroll
    for (int w = 0; w < 8; w++) tot += wredf[w];
    float inv = 1.0f / tot;

    // ---- rel_v buckets ----
    if (tid >= 1 && tid < 128) {
        int j = i + MAXREL - tid;
        float v = 0.f;
        if (j >= 0 && j < NN) {
            float e = sbuf[j];
            if (e >= 0.f) v = e * inv;
        }
        rbin[tid] = v;
    }
    float s0 = 0.f, s128 = 0.f;
    #pragma unroll
    for (int r = 0; r < 4; r++) {
        int j = tid * 4 + r;
        float e = sbuf[j];
        float a = (e >= 0.f) ? e * inv : 0.f;
        if (j >= i + MAXREL) s0 += a;
        if (j <= i - MAXREL) s128 += a;
    }
    #pragma unroll
    for (int off = 16; off > 0; off >>= 1) {
        s0   += __shfl_xor_sync(0xffffffffu, s0, off);
        s128 += __shfl_xor_sync(0xffffffffu, s128, off);
    }
    __syncthreads();
    if (lane == 0) { wredf[wid] = s0; wredf2[wid] = s128; }
    __syncthreads();
    if (tid == 0) {
        float a = 0.f, b = 0.f;
        #pragma unroll
        for (int w = 0; w < 8; w++) { a += wredf[w]; b += wredf2[w]; }
        rbin[0] = a; rbin[MAXREL * 2] = b;
    }
    __syncthreads();

    if (tid < DHd) {
        float acc = 0.f;
        #pragma unroll
        for (int t = 0; t < VOC; t++) acc += rbin[t] * __ldg(&relv[t * DHd + tid]);
        g_ARel[(size_t)row * DHd + tid] = acc;
    }

    // ---- deterministic compaction (source order) ----
    int kc = 0;
    #pragma unroll
    for (int r = 0; r < 4; r++) if (sbuf[tid * 4 + r] >= 0.f) kc++;
    int p = kc;
    #pragma unroll
    for (int off = 1; off < 32; off <<= 1) {
        int v = __shfl_up_sync(0xffffffffu, p, off);
        if (lane >= off) p += v;
    }
    if (lane == 31) wredi[wid] = p;
    __syncthreads();
    int base = 0;
    #pragma unroll
    for (int w = 0; w < 8; w++) if (w < wid) base += wredi[w];
    int pos = base + p - kc;
    size_t cbase = (size_t)row * TOPKv;
    #pragma unroll
    for (int r = 0; r < 4; r++) {
        int j = tid * 4 + r;
        float e = sbuf[j];
        if (e >= 0.f) {
            if (pos < TOPKv) { g_CI[cbase + pos] = j; g_CW[cbase + pos] = e * inv; }
            pos++;
        }
    }
}

// =====================================================================
// Kernel 5: sparse apply with fp16 V packed as half2 per d-pair.
// (proven R10 form) grid (bh, row-half) = 128 blocks, 512 threads.
// =====================================================================
__global__ __launch_bounds__(512) void k_apply(int ord, const float* __restrict__ alphas_raw) {
    extern __shared__ char smemc[];
    unsigned* sVu = (unsigned*)smemc;
    float2*   sIW = (float2*)(smemc + 1024 * 32 * 4);

    const __half* Vin16  = (ord == 0) ? g_V16  : ((ord == 1) ? g_VA16 : g_VB16);
    __half*       Vout16 = (ord == 0) ? g_VA16 : ((ord == 1) ? g_VB16 : g_VA16);

    int bh = blockIdx.x >> 1;
    int rh = blockIdx.x & 1;
    int tid = threadIdx.x, wid = tid >> 5, lane = tid & 31;

    {
        const uint4* srcv = (const uint4*)(Vin16 + (size_t)bh * NN * DHd);
        uint4* dstv = (uint4*)sVu;
        for (int e = tid; e < 8192; e += 512) dstv[e] = srcv[e];
    }
    __syncthreads();

    int h = bh & (HH - 1);
    float araw = alphas_raw[ord * HH + h];
    float alpha = 1.0f / (1.0f + __expf(-araw));
    float2* myIW = sIW + wid * 256;

    for (int i = rh * 512 + wid; i < rh * 512 + 512; i += 16) {
        int row = bh * NN + i;
        const int*   ci = &g_CI[(size_t)row * TOPKv];
        const float* cw = &g_CW[(size_t)row * TOPKv];
        #pragma unroll
        for (int q = 0; q < 8; q++) {
            int p = q * 32 + lane;
            myIW[p] = make_float2(cw[p], __int_as_float(ci[p]));
        }
        __syncwarp();
        float2 a0 = {0.f, 0.f}, a1 = {0.f, 0.f}, a2 = {0.f, 0.f}, a3 = {0.f, 0.f};
        #pragma unroll 4
        for (int p = 0; p < TOPKv; p += 4) {
            float2 w0 = myIW[p+0], w1 = myIW[p+1], w2 = myIW[p+2], w3 = myIW[p+3];
            unsigned u0 = sVu[__float_as_int(w0.y) * 32 + lane];
            unsigned u1 = sVu[__float_as_int(w1.y) * 32 + lane];
            unsigned u2 = sVu[__float_as_int(w2.y) * 32 + lane];
            unsigned u3 = sVu[__float_as_int(w3.y) * 32 + lane];
            float2 v0 = __half22float2(*(__half2*)&u0);
            float2 v1 = __half22float2(*(__half2*)&u1);
            float2 v2 = __half22float2(*(__half2*)&u2);
            float2 v3 = __half22float2(*(__half2*)&u3);
            a0.x += w0.x * v0.x; a0.y += w0.x * v0.y;
            a1.x += w1.x * v1.x; a1.y += w1.x * v1.y;
            a2.x += w2.x * v2.x; a2.y += w2.x * v2.y;
            a3.x += w3.x * v3.x; a3.y += w3.x * v3.y;
        }
        float2 acc;
        acc.x = (a0.x + a1.x) + (a2.x + a3.x);
        acc.y = (a0.y + a1.y) + (a2.y + a3.y);
        __syncwarp();

        size_t oidx = (size_t)row * DHd + 2 * lane;
        if (ord == 0) {
            float2 ar = *(const float2*)&g_ARel[oidx];
            acc.x += ar.x; acc.y += ar.y;
        }
        __half2 hv = __floats2half2_rn(acc.x, acc.y);
        *(unsigned*)&Vout16[oidx] = *(unsigned*)&hv;
        if (ord == 0) {
            float2 rv = make_float2(alpha * acc.x, alpha * acc.y);
            *(float2*)&g_Res[oidx] = rv;
        } else {
            float2 pr = *(float2*)&g_Res[oidx];
            pr.x += alpha * acc.x;
            pr.y += alpha * acc.y;
            *(float2*)&g_Res[oidx] = pr;
        }
    }
}

// =====================================================================
// Kernel 6: out = res_flat @ Wout^T + bout.  128x128 tile, BK=16,
// reg double-buffered, FFMA2.
// =====================================================================
__global__ __launch_bounds__(256) void k_gemm_out(const float* __restrict__ W,
                                                  const float* __restrict__ bias,
                                                  float* __restrict__ out) {
    __shared__ float As[16][128];
    __shared__ float Bs[16][128];
    int tid = threadIdx.x;
    int tx = tid & 15, ty = tid >> 4;
    int m0 = blockIdx.y * 128, o0 = blockIdx.x * 128;
    u64 acc2[8][4] = {};

    int lr0 = tid >> 2, lk = (tid & 3) * 4;
    int lr1 = lr0 + 64;
    int m_0 = m0 + lr0, m_1 = m0 + lr1;
    int b_0 = m_0 >> 10, n_0 = m_0 & 1023;
    int b_1 = m_1 >> 10, n_1 = m_1 & 1023;
    const float* pb0 = &W[(size_t)(o0 + lr0) * DIMV + lk];
    const float* pb1 = &W[(size_t)(o0 + lr1) * DIMV + lk];

    auto aptr = [&](int b, int n, int k) {
        return &g_Res[((size_t)((b * HH + (k >> 6)) * NN + n)) * DHd + (k & 63)];
    };

    float4 ra0 = *(const float4*)aptr(b_0, n_0, lk);
    float4 ra1 = *(const float4*)aptr(b_1, n_1, lk);
    float4 rb0 = *(const float4*)pb0;
    float4 rb1 = *(const float4*)pb1;

    for (int k0 = 0; k0 < DIMV; k0 += 16) {
        As[lk+0][lr0] = ra0.x; As[lk+1][lr0] = ra0.y; As[lk+2][lr0] = ra0.z; As[lk+3][lr0] = ra0.w;
        As[lk+0][lr1] = ra1.x; As[lk+1][lr1] = ra1.y; As[lk+2][lr1] = ra1.z; As[lk+3][lr1] = ra1.w;
        Bs[lk+0][lr0] = rb0.x; Bs[lk+1][lr0] = rb0.y; Bs[lk+2][lr0] = rb0.z; Bs[lk+3][lr0] = rb0.w;
        Bs[lk+0][lr1] = rb1.x; Bs[lk+1][lr1] = rb1.y; Bs[lk+2][lr1] = rb1.z; Bs[lk+3][lr1] = rb1.w;
        __syncthreads();
        if (k0 + 16 < DIMV) {
            ra0 = *(const float4*)aptr(b_0, n_0, k0 + 16 + lk);
            ra1 = *(const float4*)aptr(b_1, n_1, k0 + 16 + lk);
            rb0 = *(const float4*)(pb0 + k0 + 16);
            rb1 = *(const float4*)(pb1 + k0 + 16);
        }
        #pragma unroll
        for (int k = 0; k < 16; k++) {
            float4 a0 = *(const float4*)&As[k][ty * 4];
            float4 a1 = *(const float4*)&As[k][ty * 4 + 64];
            ulonglong2 b0 = *(const ulonglong2*)&Bs[k][tx * 4];
            ulonglong2 b1 = *(const ulonglong2*)&Bs[k][tx * 4 + 64];
            u64 ad[8];
            ad[0]=dup2(a0.x); ad[1]=dup2(a0.y); ad[2]=dup2(a0.z); ad[3]=dup2(a0.w);
            ad[4]=dup2(a1.x); ad[5]=dup2(a1.y); ad[6]=dup2(a1.z); ad[7]=dup2(a1.w);
            #pragma unroll
            for (int i = 0; i < 8; i++) {
                ffma2(acc2[i][0], ad[i], b0.x);
                ffma2(acc2[i][1], ad[i], b0.y);
                ffma2(acc2[i][2], ad[i], b1.x);
                ffma2(acc2[i][3], ad[i], b1.y);
            }
        }
        __syncthreads();
    }
    #pragma unroll
    for (int ih = 0; ih < 2; ih++) {
        #pragma unroll
        for (int i = 0; i < 4; i++) {
            int m = m0 + ih * 64 + ty * 4 + i;
            #pragma unroll
            for (int jh = 0; jh < 2; jh++) {
                int o = o0 + jh * 64 + tx * 4;
                float2 lo = unpack2(acc2[ih*4+i][jh*2+0]);
                float2 hi = unpack2(acc2[ih*4+i][jh*2+1]);
                float4 v;
                v.x = lo.x + bias[o+0];
                v.y = lo.y + bias[o+1];
                v.z = hi.x + bias[o+2];
                v.w = hi.y + bias[o+3];
                *(float4*)&out[(size_t)m * DIMV + o] = v;
            }
        }
    }
}

// =====================================================================
extern "C" void kernel_launch(void* const* d_in, const int* in_sizes, int n_in,
                              void* d_out, int out_size) {
    const float* x      = (const float*)d_in[0];
    const float* Wqkv   = (const float*)d_in[1];
    const float* bqkv   = (const float*)d_in[2];
    const float* Wout   = (const float*)d_in[3];
    const float* bout   = (const float*)d_in[4];
    const float* relk   = (const float*)d_in[5];
    const float* relv   = (const float*)d_in[6];
    const float* alphas = (const float*)d_in[7];
    float* out = (float*)d_out;

    k_gemm_qkv<<<dim3(24, 32), 256>>>(x, Wqkv, bqkv);
    k_qr<<<ROWS / 32, 256>>>(relk);

    cudaFuncSetAttribute(k_scores, cudaFuncAttributeMaxDynamicSharedMemorySize, 4 * 128 * 72 * 2);
    k_scores<<<dim3(8, 8, BHH), 256, 4 * 128 * 72 * 2>>>();

    k_select<<<ROWS, 256>>>(relv);

    cudaFuncSetAttribute(k_apply, cudaFuncAttributeMaxDynamicSharedMemorySize, 163840);
    k_apply<<<BHH * 2, 512, 163840>>>(0, alphas);
    k_apply<<<BHH * 2, 512, 163840>>>(1, alphas);
    k_apply<<<BHH * 2, 512, 163840>>>(2, alphas);

    k_gemm_out<<<dim3(8, 32), 256>>>(Wout, bout, out);
}

// round 13
// speedup vs baseline: 1.1480x; 1.1480x over previous
#include <cuda_runtime.h>
#include <cuda_fp16.h>

// ---------------- problem constants ----------------
#define Bb 4
#define NN 1024
#define DIMV 1024
#define HH 16
#define DHd 64
#define VOC 129            // 2*MAXREL+1
#define MAXREL 64
#define TOPKv 256
#define BHH (Bb*HH)        // 64
#define ROWS (BHH*NN)      // 65536
#define SCALEv 0.125f      // DH^-0.5
#define MQ (Bb*NN)         // 4096 token rows
#define CQKV (3*HH*DHd)    // 3072

typedef unsigned long long u64;

// ---------------- device scratch (no allocs allowed) ----------------
__device__ float g_Q[ROWS*DHd];
__device__ __half g_Q16h[ROWS*DHd];
__device__ __half g_Q16l[ROWS*DHd];
__device__ __half g_K16h[ROWS*DHd];
__device__ __half g_K16l[ROWS*DHd];
__device__ __half g_V16[ROWS*DHd];
__device__ float g_S[(size_t)ROWS*NN];        // 256 MB scores
__device__ float g_QR[ROWS*VOC];
__device__ float g_CW[ROWS*TOPKv];
__device__ int   g_CI[ROWS*TOPKv];
__device__ float g_ARel[ROWS*DHd];
__device__ __half g_VA16[ROWS*DHd];
__device__ __half g_VB16[ROWS*DHd];
__device__ float g_Res[ROWS*DHd];
// split planes for MMA GEMMs
__device__ __half g_X16h[MQ*DIMV],  g_X16l[MQ*DIMV];
__device__ __half g_Wq16h[CQKV*DIMV], g_Wq16l[CQKV*DIMV];
__device__ __half g_Wo16h[DIMV*DIMV], g_Wo16l[DIMV*DIMV];
__device__ __half g_R16h[MQ*DIMV],  g_R16l[MQ*DIMV];   // Res flat [m][dim]

// ---------------- packed f32x2 helpers ----------------
__device__ __forceinline__ void ffma2(u64 &d, u64 a, u64 b) {
    asm("fma.rn.f32x2 %0, %1, %2, %0;" : "+l"(d) : "l"(a), "l"(b));
}
__device__ __forceinline__ u64 dup2(float x) {
    u64 r; asm("mov.b64 %0, {%1, %1};" : "=l"(r) : "f"(x)); return r;
}
__device__ __forceinline__ float2 unpack2(u64 v) {
    float2 f; asm("mov.b64 {%0, %1}, %2;" : "=f"(f.x), "=f"(f.y) : "l"(v)); return f;
}
__device__ __forceinline__ unsigned smem_u32(const void* p) {
    unsigned a;
    asm("{ .reg .u64 t; cvta.to.shared.u64 t, %1; cvt.u32.u64 %0, t; }" : "=r"(a) : "l"(p));
    return a;
}
__device__ __forceinline__ void split16(float f, __half &h, __half &l) {
    h = __float2half_rn(f);
    l = __float2half_rn(f - __half2float(h));
}

// =====================================================================
// Kernel 0: split fp32 array -> fp16 hi/lo planes (vectorized)
// =====================================================================
__global__ void k_split(const float* __restrict__ src, __half* __restrict__ ph,
                        __half* __restrict__ pl, int n4) {
    int idx = blockIdx.x * blockDim.x + threadIdx.x;
    if (idx >= n4) return;
    float4 v = *(const float4*)&src[idx * 4];
    __half hh[4], hl[4];
    split16(v.x, hh[0], hl[0]);
    split16(v.y, hh[1], hl[1]);
    split16(v.z, hh[2], hl[2]);
    split16(v.w, hh[3], hl[3]);
    *(uint2*)&ph[idx * 4] = make_uint2(*(unsigned*)&hh[0], *(unsigned*)&hh[2]);
    *(uint2*)&pl[idx * 4] = make_uint2(*(unsigned*)&hl[0], *(unsigned*)&hl[2]);
}

// =====================================================================
// Kernel 1: qkv GEMM via split-fp16 MMA (acc = AhBh + AhBl + AlBh).
// 128x128 tile, BK=64 chunks x16, 8 warps 4(m)x2(n).
// Epilogue scatters into Q (fp32 + hi/lo), K (hi/lo), V (fp16).
// grid (24, 32), 256 threads, dyn smem 4*128*72 halfs.
// =====================================================================
__global__ __launch_bounds__(256) void k_gemm_qkv(const float* __restrict__ bias) {
    extern __shared__ __half sdyn[];
    __half (*sAh)[72] = (__half(*)[72])(sdyn);
    __half (*sAl)[72] = (__half(*)[72])(sdyn + 128 * 72);
    __half (*sBh)[72] = (__half(*)[72])(sdyn + 2 * 128 * 72);
    __half (*sBl)[72] = (__half(*)[72])(sdyn + 3 * 128 * 72);
    int tid = threadIdx.x;
    int lane = tid & 31, wid = tid >> 5;
    int warp_m = wid & 3, warp_n = wid >> 2;
    int m0 = blockIdx.y * 128, c0 = blockIdx.x * 128;

    float acc[2][8][4];
    #pragma unroll
    for (int ma = 0; ma < 2; ma++)
        #pragma unroll
        for (int na = 0; na < 8; na++)
            #pragma unroll
            for (int q = 0; q < 4; q++) acc[ma][na][q] = 0.f;

    int lm = lane >> 3, lr = lane & 7;
    int aRowOff = (lm & 1) * 8 + lr;
    int aColOff = (lm >> 1) * 8;
    int bRowOff = (lm >> 1) * 8 + lr;
    int bColOff = (lm & 1) * 8;

    for (int kc = 0; kc < DIMV; kc += 64) {
        for (int e = tid; e < 1024; e += 256) {
            int r = e >> 3, s = (e & 7) * 8;
            *(uint4*)&sAh[r][s] = *(const uint4*)&g_X16h[(size_t)(m0 + r) * DIMV + kc + s];
            *(uint4*)&sAl[r][s] = *(const uint4*)&g_X16l[(size_t)(m0 + r) * DIMV + kc + s];
            *(uint4*)&sBh[r][s] = *(const uint4*)&g_Wq16h[(size_t)(c0 + r) * DIMV + kc + s];
            *(uint4*)&sBl[r][s] = *(const uint4*)&g_Wq16l[(size_t)(c0 + r) * DIMV + kc + s];
        }
        __syncthreads();
        #pragma unroll
        for (int kk = 0; kk < 4; kk++) {
            int kbase = kk * 16;
            unsigned ah[2][4], al[2][4];
            #pragma unroll
            for (int ma = 0; ma < 2; ma++) {
                int rowq = warp_m * 32 + ma * 16 + aRowOff;
                unsigned ad = smem_u32(&sAh[rowq][kbase + aColOff]);
                asm volatile("ldmatrix.sync.aligned.m8n8.x4.shared.b16 {%0,%1,%2,%3}, [%4];"
                             : "=r"(ah[ma][0]), "=r"(ah[ma][1]), "=r"(ah[ma][2]), "=r"(ah[ma][3]) : "r"(ad));
                ad = smem_u32(&sAl[rowq][kbase + aColOff]);
                asm volatile("ldmatrix.sync.aligned.m8n8.x4.shared.b16 {%0,%1,%2,%3}, [%4];"
                             : "=r"(al[ma][0]), "=r"(al[ma][1]), "=r"(al[ma][2]), "=r"(al[ma][3]) : "r"(ad));
            }
            unsigned bh_[8][2], bl_[8][2];
            #pragma unroll
            for (int np = 0; np < 4; np++) {
                int rowk = warp_n * 64 + np * 16 + bRowOff;
                unsigned r0, r1, r2, r3;
                unsigned ad = smem_u32(&sBh[rowk][kbase + bColOff]);
                asm volatile("ldmatrix.sync.aligned.m8n8.x4.shared.b16 {%0,%1,%2,%3}, [%4];"
                             : "=r"(r0), "=r"(r1), "=r"(r2), "=r"(r3) : "r"(ad));
                bh_[np*2+0][0] = r0; bh_[np*2+0][1] = r1;
                bh_[np*2+1][0] = r2; bh_[np*2+1][1] = r3;
                ad = smem_u32(&sBl[rowk][kbase + bColOff]);
                asm volatile("ldmatrix.sync.aligned.m8n8.x4.shared.b16 {%0,%1,%2,%3}, [%4];"
                             : "=r"(r0), "=r"(r1), "=r"(r2), "=r"(r3) : "r"(ad));
                bl_[np*2+0][0] = r0; bl_[np*2+0][1] = r1;
                bl_[np*2+1][0] = r2; bl_[np*2+1][1] = r3;
            }
            #pragma unroll
            for (int ma = 0; ma < 2; ma++) {
                #pragma unroll
                for (int na = 0; na < 8; na++) {
                    asm volatile("mma.sync.aligned.m16n8k16.row.col.f32.f16.f16.f32 "
                        "{%0,%1,%2,%3}, {%4,%5,%6,%7}, {%8,%9}, {%0,%1,%2,%3};"
                        : "+f"(acc[ma][na][0]), "+f"(acc[ma][na][1]), "+f"(acc[ma][na][2]), "+f"(acc[ma][na][3])
                        : "r"(ah[ma][0]), "r"(ah[ma][1]), "r"(ah[ma][2]), "r"(ah[ma][3]),
                          "r"(bh_[na][0]), "r"(bh_[na][1]));
                    asm volatile("mma.sync.aligned.m16n8k16.row.col.f32.f16.f16.f32 "
                        "{%0,%1,%2,%3}, {%4,%5,%6,%7}, {%8,%9}, {%0,%1,%2,%3};"
                        : "+f"(acc[ma][na][0]), "+f"(acc[ma][na][1]), "+f"(acc[ma][na][2]), "+f"(acc[ma][na][3])
                        : "r"(ah[ma][0]), "r"(ah[ma][1]), "r"(ah[ma][2]), "r"(ah[ma][3]),
                          "r"(bl_[na][0]), "r"(bl_[na][1]));
                    asm volatile("mma.sync.aligned.m16n8k16.row.col.f32.f16.f16.f32 "
                        "{%0,%1,%2,%3}, {%4,%5,%6,%7}, {%8,%9}, {%0,%1,%2,%3};"
                        : "+f"(acc[ma][na][0]), "+f"(acc[ma][na][1]), "+f"(acc[ma][na][2]), "+f"(acc[ma][na][3])
                        : "r"(al[ma][0]), "r"(al[ma][1]), "r"(al[ma][2]), "r"(al[ma][3]),
                          "r"(bh_[na][0]), "r"(bh_[na][1]));
                }
            }
        }
        __syncthreads();
    }

    // epilogue: bias + scatter
    int g = lane >> 2, tg = lane & 3;
    #pragma unroll
    for (int ma = 0; ma < 2; ma++) {
        #pragma unroll
        for (int half = 0; half < 2; half++) {
            int m = m0 + warp_m * 32 + ma * 16 + g + half * 8;
            int b = m >> 10, n = m & 1023;
            #pragma unroll
            for (int na = 0; na < 8; na++) {
                int c = c0 + warp_n * 64 + na * 8 + tg * 2;
                float2 v;
                v.x = acc[ma][na][half*2+0] + bias[c];
                v.y = acc[ma][na][half*2+1] + bias[c+1];
                int part = c >> 10;
                int hc = c & 1023;
                int h = hc >> 6, dh = hc & 63;
                size_t idx = ((size_t)((b * HH + h) * NN + n)) * DHd + dh;
                if (part == 2) {
                    __half2 hv = __floats2half2_rn(v.x, v.y);
                    *(unsigned*)&g_V16[idx] = *(unsigned*)&hv;
                } else {
                    __half h0, l0, h1, l1;
                    split16(v.x, h0, l0);
                    split16(v.y, h1, l1);
                    __half2 hp = __halves2half2(h0, h1);
                    __half2 lp = __halves2half2(l0, l1);
                    if (part == 0) {
                        *(float2*)&g_Q[idx] = v;
                        *(unsigned*)&g_Q16h[idx] = *(unsigned*)&hp;
                        *(unsigned*)&g_Q16l[idx] = *(unsigned*)&lp;
                    } else {
                        *(unsigned*)&g_K16h[idx] = *(unsigned*)&hp;
                        *(unsigned*)&g_K16l[idx] = *(unsigned*)&lp;
                    }
                }
            }
        }
    }
}

// =====================================================================
// Kernel 2: QR[row][t] = Q[row] . rel_k_emb[t]  (fp32, smem-staged)
// =====================================================================
__global__ __launch_bounds__(256) void k_qr(const float* __restrict__ relk) {
    __shared__ float sQ[32][68];
    __shared__ float srk[64][132];
    int tid = threadIdx.x;
    int row0 = blockIdx.x * 32;
    for (int e = tid; e < 32 * 64; e += 256) {
        int r = e >> 6, d = e & 63;
        sQ[r][d] = g_Q[(size_t)(row0 + r) * DHd + d];
    }
    for (int e = tid; e < 64 * 132; e += 256) {
        int d = e / 132, t = e % 132;
        srk[d][t] = (t < VOC) ? relk[t * DHd + d] : 0.f;
    }
    __syncthreads();
    for (int g = tid; g < 32 * 33; g += 256) {
        int r = g / 33, tt = g % 33;
        u64 a01 = 0, a23 = 0;
        #pragma unroll 16
        for (int d = 0; d < 64; d++) {
            u64 qd = dup2(sQ[r][d]);
            ulonglong2 f = *(const ulonglong2*)&srk[d][tt * 4];
            ffma2(a01, qd, f.x);
            ffma2(a23, qd, f.y);
        }
        float2 lo = unpack2(a01), hi = unpack2(a23);
        size_t base = (size_t)(row0 + r) * VOC;
        int t0 = tt * 4;
        if (tt < 32) {
            g_QR[base + t0 + 0] = lo.x;
            g_QR[base + t0 + 1] = lo.y;
            g_QR[base + t0 + 2] = hi.x;
            g_QR[base + t0 + 3] = hi.y;
        } else {
            g_QR[base + 128] = lo.x;
        }
    }
}

// =====================================================================
// Kernel 3: S = SCALE*(Q.K^T) + QR gather via split-fp16 MMA (proven).
// grid (8, 8, 64), 256 threads, dyn smem 4 tiles.
// =====================================================================
__global__ __launch_bounds__(256) void k_scores() {
    extern __shared__ __half sdyn[];
    __half (*sQh)[72] = (__half(*)[72])(sdyn);
    __half (*sQl)[72] = (__half(*)[72])(sdyn + 128 * 72);
    __half (*sKh)[72] = (__half(*)[72])(sdyn + 2 * 128 * 72);
    __half (*sKl)[72] = (__half(*)[72])(sdyn + 3 * 128 * 72);
    int tid = threadIdx.x;
    int lane = tid & 31, wid = tid >> 5;
    int warp_m = wid & 3;
    int warp_n = wid >> 2;
    int bh = blockIdx.z;
    int i0 = blockIdx.y * 128, j0 = blockIdx.x * 128;

    {
        const __half* gqh = g_Q16h + (size_t)(bh * NN + i0) * DHd;
        const __half* gql = g_Q16l + (size_t)(bh * NN + i0) * DHd;
        const __half* gkh = g_K16h + (size_t)(bh * NN + j0) * DHd;
        const __half* gkl = g_K16l + (size_t)(bh * NN + j0) * DHd;
        for (int e = tid; e < 1024; e += 256) {
            int r = e >> 3, s = (e & 7) * 8;
            *(uint4*)&sQh[r][s] = *(const uint4*)&gqh[r * DHd + s];
            *(uint4*)&sQl[r][s] = *(const uint4*)&gql[r * DHd + s];
            *(uint4*)&sKh[r][s] = *(const uint4*)&gkh[r * DHd + s];
            *(uint4*)&sKl[r][s] = *(const uint4*)&gkl[r * DHd + s];
        }
    }
    __syncthreads();

    float acc[2][8][4];
    #pragma unroll
    for (int ma = 0; ma < 2; ma++)
        #pragma unroll
        for (int na = 0; na < 8; na++)
            #pragma unroll
            for (int q = 0; q < 4; q++) acc[ma][na][q] = 0.f;

    int lm = lane >> 3;
    int lr = lane & 7;
    int aRowOff = (lm & 1) * 8 + lr;
    int aColOff = (lm >> 1) * 8;
    int bRowOff = (lm >> 1) * 8 + lr;
    int bColOff = (lm & 1) * 8;

    #pragma unroll
    for (int kk = 0; kk < 4; kk++) {
        int kbase = kk * 16;
        unsigned ah[2][4], al[2][4];
        #pragma unroll
        for (int ma = 0; ma < 2; ma++) {
            int rowq = warp_m * 32 + ma * 16 + aRowOff;
            unsigned addrh = smem_u32(&sQh[rowq][kbase + aColOff]);
            asm volatile("ldmatrix.sync.aligned.m8n8.x4.shared.b16 {%0,%1,%2,%3}, [%4];"
                         : "=r"(ah[ma][0]), "=r"(ah[ma][1]), "=r"(ah[ma][2]), "=r"(ah[ma][3])
                         : "r"(addrh));
            unsigned addrl = smem_u32(&sQl[rowq][kbase + aColOff]);
            asm volatile("ldmatrix.sync.aligned.m8n8.x4.shared.b16 {%0,%1,%2,%3}, [%4];"
                         : "=r"(al[ma][0]), "=r"(al[ma][1]), "=r"(al[ma][2]), "=r"(al[ma][3])
                         : "r"(addrl));
        }
        unsigned bh_[8][2], bl_[8][2];
        #pragma unroll
        for (int np = 0; np < 4; np++) {
            int rowk = warp_n * 64 + np * 16 + bRowOff;
            unsigned r0, r1, r2, r3;
            unsigned addrh = smem_u32(&sKh[rowk][kbase + bColOff]);
            asm volatile("ldmatrix.sync.aligned.m8n8.x4.shared.b16 {%0,%1,%2,%3}, [%4];"
                         : "=r"(r0), "=r"(r1), "=r"(r2), "=r"(r3) : "r"(addrh));
            bh_[np*2+0][0] = r0; bh_[np*2+0][1] = r1;
            bh_[np*2+1][0] = r2; bh_[np*2+1][1] = r3;
            unsigned addrl = smem_u32(&sKl[rowk][kbase + bColOff]);
            asm volatile("ldmatrix.sync.aligned.m8n8.x4.shared.b16 {%0,%1,%2,%3}, [%4];"
                         : "=r"(r0), "=r"(r1), "=r"(r2), "=r"(r3) : "r"(addrl));
            bl_[np*2+0][0] = r0; bl_[np*2+0][1] = r1;
            bl_[np*2+1][0] = r2; bl_[np*2+1][1] = r3;
        }
        #pragma unroll
        for (int ma = 0; ma < 2; ma++) {
            #pragma unroll
            for (int na = 0; na < 8; na++) {
                asm volatile("mma.sync.aligned.m16n8k16.row.col.f32.f16.f16.f32 "
                    "{%0,%1,%2,%3}, {%4,%5,%6,%7}, {%8,%9}, {%0,%1,%2,%3};"
                    : "+f"(acc[ma][na][0]), "+f"(acc[ma][na][1]), "+f"(acc[ma][na][2]), "+f"(acc[ma][na][3])
                    : "r"(ah[ma][0]), "r"(ah[ma][1]), "r"(ah[ma][2]), "r"(ah[ma][3]),
                      "r"(bh_[na][0]), "r"(bh_[na][1]));
                asm volatile("mma.sync.aligned.m16n8k16.row.col.f32.f16.f16.f32 "
                    "{%0,%1,%2,%3}, {%4,%5,%6,%7}, {%8,%9}, {%0,%1,%2,%3};"
                    : "+f"(acc[ma][na][0]), "+f"(acc[ma][na][1]), "+f"(acc[ma][na][2]), "+f"(acc[ma][na][3])
                    : "r"(ah[ma][0]), "r"(ah[ma][1]), "r"(ah[ma][2]), "r"(ah[ma][3]),
                      "r"(bl_[na][0]), "r"(bl_[na][1]));
                asm volatile("mma.sync.aligned.m16n8k16.row.col.f32.f16.f16.f32 "
                    "{%0,%1,%2,%3}, {%4,%5,%6,%7}, {%8,%9}, {%0,%1,%2,%3};"
                    : "+f"(acc[ma][na][0]), "+f"(acc[ma][na][1]), "+f"(acc[ma][na][2]), "+f"(acc[ma][na][3])
                    : "r"(al[ma][0]), "r"(al[ma][1]), "r"(al[ma][2]), "r"(al[ma][3]),
                      "r"(bh_[na][0]), "r"(bh_[na][1]));
            }
        }
    }

    int g = lane >> 2, tg = lane & 3;
    #pragma unroll
    for (int ma = 0; ma < 2; ma++) {
        int rowA = i0 + warp_m * 32 + ma * 16 + g;
        #pragma unroll
        for (int half = 0; half < 2; half++) {
            int ii = rowA + half * 8;
            const float* qr = &g_QR[(size_t)(bh * NN + ii) * VOC];
            size_t sbase = ((size_t)(bh * NN + ii)) * NN;
            #pragma unroll
            for (int na = 0; na < 8; na++) {
                int jj = j0 + warp_n * 64 + na * 8 + tg * 2;
                int d0 = ii - jj;
                d0 = d0 < -MAXREL ? -MAXREL : (d0 > MAXREL ? MAXREL : d0);
                int d1 = ii - (jj + 1);
                d1 = d1 < -MAXREL ? -MAXREL : (d1 > MAXREL ? MAXREL : d1);
                float2 v;
                v.x = acc[ma][na][half*2+0] * SCALEv + qr[d0 + MAXREL];
                v.y = acc[ma][na][half*2+1] * SCALEv + qr[d1 + MAXREL];
                *(float2*)&g_S[sbase + jj] = v;
            }
        }
    }
}

// float -> order-preserving uint key
__device__ __forceinline__ unsigned ftokey(float f) {
    unsigned u = __float_as_uint(f);
    return (u & 0x80000000u) ? ~u : (u | 0x80000000u);
}

// =====================================================================
// Kernel 4 (fused): radix-select + masked softmax + compaction + ARel.
// (proven form) One block (256 threads) per score row.
// =====================================================================
__global__ __launch_bounds__(256) void k_select(const float* __restrict__ relv) {
    __shared__ float sbuf[1024];
    __shared__ int   hist[256];
    __shared__ float wredf[8];
    __shared__ float wredf2[8];
    __shared__ int   wredi[8];
    __shared__ float rbin[VOC];
    __shared__ unsigned sh_selb;
    __shared__ int      sh_rem;

    int row = blockIdx.x;
    int tid = threadIdx.x;
    int lane = tid & 31, wid = tid >> 5;
    int i = row & (NN - 1);
    const float* src = &g_S[(size_t)row * NN];

    float lv[4]; unsigned kv[4];
    #pragma unroll
    for (int r = 0; r < 4; r++) {
        int j = tid * 4 + r;
        lv[r] = src[j];
        kv[r] = ftokey(lv[r]);
    }

    float m = fmaxf(fmaxf(lv[0], lv[1]), fmaxf(lv[2], lv[3]));
    #pragma unroll
    for (int off = 16; off > 0; off >>= 1)
        m = fmaxf(m, __shfl_xor_sync(0xffffffffu, m, off));
    if (lane == 0) wredf[wid] = m;
    __syncthreads();
    float rmax = wredf[0];
    #pragma unroll
    for (int w = 1; w < 8; w++) rmax = fmaxf(rmax, wredf[w]);

    unsigned prefix = 0;
    int need = TOPKv;
    for (int round = 3; round >= 0; round--) {
        hist[tid] = 0;
        __syncthreads();
        unsigned mask = (round == 3) ? 0u : (0xFFFFFFFFu << ((round + 1) * 8));
        #pragma unroll
        for (int r = 0; r < 4; r++) {
            if ((kv[r] & mask) == prefix)
                atomicAdd(&hist[(kv[r] >> (round * 8)) & 255], 1);
        }
        __syncthreads();
        int h = hist[tid];
        int s = h;
        #pragma unroll
        for (int off = 1; off < 32; off <<= 1) {
            int v = __shfl_down_sync(0xffffffffu, s, off);
            if (lane + off < 32) s += v;
        }
        int wtot = __shfl_sync(0xffffffffu, s, 0);
        if (lane == 0) wredi[wid] = wtot;
        __syncthreads();
        int tail = 0;
        #pragma unroll
        for (int w = 0; w < 8; w++) if (w > wid) tail += wredi[w];
        int Sb = s + tail;
        int Sb1 = Sb - h;
        if (Sb >= need && Sb1 < need) { sh_selb = (unsigned)tid; sh_rem = Sb1; }
        __syncthreads();
        prefix |= sh_selb << (round * 8);
        need -= sh_rem;
        __syncthreads();
    }
    unsigned thrkey = prefix;

    float lsum = 0.f;
    #pragma unroll
    for (int r = 0; r < 4; r++) {
        int j = tid * 4 + r;
        float e;
        if (kv[r] >= thrkey) { e = __expf(lv[r] - rmax); lsum += e; }
        else e = -1.0f;
        sbuf[j] = e;
    }
    float ws = lsum;
    #pragma unroll
    for (int off = 16; off > 0; off >>= 1)
        ws += __shfl_xor_sync(0xffffffffu, ws, off);
    if (lane == 0) wredf[wid] = ws;
    __syncthreads();
    float tot = 0.f;
    #pragma unroll
    for (int w = 0; w < 8; w++) tot += wredf[w];
    float inv = 1.0f / tot;

    if (tid >= 1 && tid < 128) {
        int j = i + MAXREL - tid;
        float v = 0.f;
        if (j >= 0 && j < NN) {
            float e = sbuf[j];
            if (e >= 0.f) v = e * inv;
        }
        rbin[tid] = v;
    }
    float s0 = 0.f, s128 = 0.f;
    #pragma unroll
    for (int r = 0; r < 4; r++) {
        int j = tid * 4 + r;
        float e = sbuf[j];
        float a = (e >= 0.f) ? e * inv : 0.f;
        if (j >= i + MAXREL) s0 += a;
        if (j <= i - MAXREL) s128 += a;
    }
    #pragma unroll
    for (int off = 16; off > 0; off >>= 1) {
        s0   += __shfl_xor_sync(0xffffffffu, s0, off);
        s128 += __shfl_xor_sync(0xffffffffu, s128, off);
    }
    __syncthreads();
    if (lane == 0) { wredf[wid] = s0; wredf2[wid] = s128; }
    __syncthreads();
    if (tid == 0) {
        float a = 0.f, b = 0.f;
        #pragma unroll
        for (int w = 0; w < 8; w++) { a += wredf[w]; b += wredf2[w]; }
        rbin[0] = a; rbin[MAXREL * 2] = b;
    }
    __syncthreads();

    if (tid < DHd) {
        float acc = 0.f;
        #pragma unroll
        for (int t = 0; t < VOC; t++) acc += rbin[t] * __ldg(&relv[t * DHd + tid]);
        g_ARel[(size_t)row * DHd + tid] = acc;
    }

    int kc = 0;
    #pragma unroll
    for (int r = 0; r < 4; r++) if (sbuf[tid * 4 + r] >= 0.f) kc++;
    int p = kc;
    #pragma unroll
    for (int off = 1; off < 32; off <<= 1) {
        int v = __shfl_up_sync(0xffffffffu, p, off);
        if (lane >= off) p += v;
    }
    if (lane == 31) wredi[wid] = p;
    __syncthreads();
    int base = 0;
    #pragma unroll
    for (int w = 0; w < 8; w++) if (w < wid) base += wredi[w];
    int pos = base + p - kc;
    size_t cbase = (size_t)row * TOPKv;
    #pragma unroll
    for (int r = 0; r < 4; r++) {
        int j = tid * 4 + r;
        float e = sbuf[j];
        if (e >= 0.f) {
            if (pos < TOPKv) { g_CI[cbase + pos] = j; g_CW[cbase + pos] = e * inv; }
            pos++;
        }
    }
}

// =====================================================================
// Kernel 5: sparse apply with fp16 V (proven). ord==2 additionally emits
// Res in FLAT [m][dim] layout as fp16 hi/lo for the MMA out-GEMM.
// grid (bh, row-half) = 128 blocks, 512 threads.
// =====================================================================
__global__ __launch_bounds__(512) void k_apply(int ord, const float* __restrict__ alphas_raw) {
    extern __shared__ char smemc[];
    unsigned* sVu = (unsigned*)smemc;
    float2*   sIW = (float2*)(smemc + 1024 * 32 * 4);

    const __half* Vin16  = (ord == 0) ? g_V16  : ((ord == 1) ? g_VA16 : g_VB16);
    __half*       Vout16 = (ord == 0) ? g_VA16 : ((ord == 1) ? g_VB16 : g_VA16);

    int bh = blockIdx.x >> 1;
    int rh = blockIdx.x & 1;
    int tid = threadIdx.x, wid = tid >> 5, lane = tid & 31;

    {
        const uint4* srcv = (const uint4*)(Vin16 + (size_t)bh * NN * DHd);
        uint4* dstv = (uint4*)sVu;
        for (int e = tid; e < 8192; e += 512) dstv[e] = srcv[e];
    }
    __syncthreads();

    int h = bh & (HH - 1);
    int bb = bh >> 4;
    float araw = alphas_raw[ord * HH + h];
    float alpha = 1.0f / (1.0f + __expf(-araw));
    float2* myIW = sIW + wid * 256;

    for (int i = rh * 512 + wid; i < rh * 512 + 512; i += 16) {
        int row = bh * NN + i;
        const int*   ci = &g_CI[(size_t)row * TOPKv];
        const float* cw = &g_CW[(size_t)row * TOPKv];
        #pragma unroll
        for (int q = 0; q < 8; q++) {
            int p = q * 32 + lane;
            myIW[p] = make_float2(cw[p], __int_as_float(ci[p]));
        }
        __syncwarp();
        float2 a0 = {0.f, 0.f}, a1 = {0.f, 0.f}, a2 = {0.f, 0.f}, a3 = {0.f, 0.f};
        #pragma unroll 4
        for (int p = 0; p < TOPKv; p += 4) {
            float2 w0 = myIW[p+0], w1 = myIW[p+1], w2 = myIW[p+2], w3 = myIW[p+3];
            unsigned u0 = sVu[__float_as_int(w0.y) * 32 + lane];
            unsigned u1 = sVu[__float_as_int(w1.y) * 32 + lane];
            unsigned u2 = sVu[__float_as_int(w2.y) * 32 + lane];
            unsigned u3 = sVu[__float_as_int(w3.y) * 32 + lane];
            float2 v0 = __half22float2(*(__half2*)&u0);
            float2 v1 = __half22float2(*(__half2*)&u1);
            float2 v2 = __half22float2(*(__half2*)&u2);
            float2 v3 = __half22float2(*(__half2*)&u3);
            a0.x += w0.x * v0.x; a0.y += w0.x * v0.y;
            a1.x += w1.x * v1.x; a1.y += w1.x * v1.y;
            a2.x += w2.x * v2.x; a2.y += w2.x * v2.y;
            a3.x += w3.x * v3.x; a3.y += w3.x * v3.y;
        }
        float2 acc;
        acc.x = (a0.x + a1.x) + (a2.x + a3.x);
        acc.y = (a0.y + a1.y) + (a2.y + a3.y);
        __syncwarp();

        size_t oidx = (size_t)row * DHd + 2 * lane;
        if (ord == 0) {
            float2 ar = *(const float2*)&g_ARel[oidx];
            acc.x += ar.x; acc.y += ar.y;
        }
        __half2 hv = __floats2half2_rn(acc.x, acc.y);
        *(unsigned*)&Vout16[oidx] = *(unsigned*)&hv;
        if (ord == 0) {
            float2 rv = make_float2(alpha * acc.x, alpha * acc.y);
            *(float2*)&g_Res[oidx] = rv;
        } else if (ord == 1) {
            float2 pr = *(float2*)&g_Res[oidx];
            pr.x += alpha * acc.x;
            pr.y += alpha * acc.y;
            *(float2*)&g_Res[oidx] = pr;
        } else {
            float2 pr = *(float2*)&g_Res[oidx];
            pr.x += alpha * acc.x;
            pr.y += alpha * acc.y;
            // flat layout [m][dim]: m = bb*1024 + i, dim = h*64 + 2*lane
            size_t fidx = ((size_t)(bb * 1024 + i)) * DIMV + h * DHd + 2 * lane;
            __half h0, l0, h1, l1;
            split16(pr.x, h0, l0);
            split16(pr.y, h1, l1);
            __half2 hp = __halves2half2(h0, h1);
            __half2 lp = __halves2half2(l0, l1);
            *(unsigned*)&g_R16h[fidx] = *(unsigned*)&hp;
            *(unsigned*)&g_R16l[fidx] = *(unsigned*)&lp;
        }
    }
}

// =====================================================================
// Kernel 6: out = Res_flat @ Wout^T + bout via split-fp16 MMA.
// grid (8, 32), 256 threads, dyn smem 4*128*72 halfs.
// =====================================================================
__global__ __launch_bounds__(256) void k_gemm_out(const float* __restrict__ bias,
                                                  float* __restrict__ out) {
    extern __shared__ __half sdyn[];
    __half (*sAh)[72] = (__half(*)[72])(sdyn);
    __half (*sAl)[72] = (__half(*)[72])(sdyn + 128 * 72);
    __half (*sBh)[72] = (__half(*)[72])(sdyn + 2 * 128 * 72);
    __half (*sBl)[72] = (__half(*)[72])(sdyn + 3 * 128 * 72);
    int tid = threadIdx.x;
    int lane = tid & 31, wid = tid >> 5;
    int warp_m = wid & 3, warp_n = wid >> 2;
    int m0 = blockIdx.y * 128, o0 = blockIdx.x * 128;

    float acc[2][8][4];
    #pragma unroll
    for (int ma = 0; ma < 2; ma++)
        #pragma unroll
        for (int na = 0; na < 8; na++)
            #pragma unroll
            for (int q = 0; q < 4; q++) acc[ma][na][q] = 0.f;

    int lm = lane >> 3, lr = lane & 7;
    int aRowOff = (lm & 1) * 8 + lr;
    int aColOff = (lm >> 1) * 8;
    int bRowOff = (lm >> 1) * 8 + lr;
    int bColOff = (lm & 1) * 8;

    for (int kc = 0; kc < DIMV; kc += 64) {
        for (int e = tid; e < 1024; e += 256) {
            int r = e >> 3, s = (e & 7) * 8;
            *(uint4*)&sAh[r][s] = *(const uint4*)&g_R16h[(size_t)(m0 + r) * DIMV + kc + s];
            *(uint4*)&sAl[r][s] = *(const uint4*)&g_R16l[(size_t)(m0 + r) * DIMV + kc + s];
            *(uint4*)&sBh[r][s] = *(const uint4*)&g_Wo16h[(size_t)(o0 + r) * DIMV + kc + s];
            *(uint4*)&sBl[r][s] = *(const uint4*)&g_Wo16l[(size_t)(o0 + r) * DIMV + kc + s];
        }
        __syncthreads();
        #pragma unroll
        for (int kk = 0; kk < 4; kk++) {
            int kbase = kk * 16;
            unsigned ah[2][4], al[2][4];
            #pragma unroll
            for (int ma = 0; ma < 2; ma++) {
                int rowq = warp_m * 32 + ma * 16 + aRowOff;
                unsigned ad = smem_u32(&sAh[rowq][kbase + aColOff]);
                asm volatile("ldmatrix.sync.aligned.m8n8.x4.shared.b16 {%0,%1,%2,%3}, [%4];"
                             : "=r"(ah[ma][0]), "=r"(ah[ma][1]), "=r"(ah[ma][2]), "=r"(ah[ma][3]) : "r"(ad));
                ad = smem_u32(&sAl[rowq][kbase + aColOff]);
                asm volatile("ldmatrix.sync.aligned.m8n8.x4.shared.b16 {%0,%1,%2,%3}, [%4];"
                             : "=r"(al[ma][0]), "=r"(al[ma][1]), "=r"(al[ma][2]), "=r"(al[ma][3]) : "r"(ad));
            }
            unsigned bh_[8][2], bl_[8][2];
            #pragma unroll
            for (int np = 0; np < 4; np++) {
                int rowk = warp_n * 64 + np * 16 + bRowOff;
                unsigned r0, r1, r2, r3;
                unsigned ad = smem_u32(&sBh[rowk][kbase + bColOff]);
                asm volatile("ldmatrix.sync.aligned.m8n8.x4.shared.b16 {%0,%1,%2,%3}, [%4];"
                             : "=r"(r0), "=r"(r1), "=r"(r2), "=r"(r3) : "r"(ad));
                bh_[np*2+0][0] = r0; bh_[np*2+0][1] = r1;
                bh_[np*2+1][0] = r2; bh_[np*2+1][1] = r3;
                ad = smem_u32(&sBl[rowk][kbase + bColOff]);
                asm volatile("ldmatrix.sync.aligned.m8n8.x4.shared.b16 {%0,%1,%2,%3}, [%4];"
                             : "=r"(r0), "=r"(r1), "=r"(r2), "=r"(r3) : "r"(ad));
                bl_[np*2+0][0] = r0; bl_[np*2+0][1] = r1;
                bl_[np*2+1][0] = r2; bl_[np*2+1][1] = r3;
            }
            #pragma unroll
            for (int ma = 0; ma < 2; ma++) {
                #pragma unroll
                for (int na = 0; na < 8; na++) {
                    asm volatile("mma.sync.aligned.m16n8k16.row.col.f32.f16.f16.f32 "
                        "{%0,%1,%2,%3}, {%4,%5,%6,%7}, {%8,%9}, {%0,%1,%2,%3};"
                        : "+f"(acc[ma][na][0]), "+f"(acc[ma][na][1]), "+f"(acc[ma][na][2]), "+f"(acc[ma][na][3])
                        : "r"(ah[ma][0]), "r"(ah[ma][1]), "r"(ah[ma][2]), "r"(ah[ma][3]),
                          "r"(bh_[na][0]), "r"(bh_[na][1]));
                    asm volatile("mma.sync.aligned.m16n8k16.row.col.f32.f16.f16.f32 "
                        "{%0,%1,%2,%3}, {%4,%5,%6,%7}, {%8,%9}, {%0,%1,%2,%3};"
                        : "+f"(acc[ma][na][0]), "+f"(acc[ma][na][1]), "+f"(acc[ma][na][2]), "+f"(acc[ma][na][3])
                        : "r"(ah[ma][0]), "r"(ah[ma][1]), "r"(ah[ma][2]), "r"(ah[ma][3]),
                          "r"(bl_[na][0]), "r"(bl_[na][1]));
                    asm volatile("mma.sync.aligned.m16n8k16.row.col.f32.f16.f16.f32 "
                        "{%0,%1,%2,%3}, {%4,%5,%6,%7}, {%8,%9}, {%0,%1,%2,%3};"
                        : "+f"(acc[ma][na][0]), "+f"(acc[ma][na][1]), "+f"(acc[ma][na][2]), "+f"(acc[ma][na][3])
                        : "r"(al[ma][0]), "r"(al[ma][1]), "r"(al[ma][2]), "r"(al[ma][3]),
                          "r"(bh_[na][0]), "r"(bh_[na][1]));
                }
            }
        }
        __syncthreads();
    }

    int g = lane >> 2, tg = lane & 3;
    #pragma unroll
    for (int ma = 0; ma < 2; ma++) {
        #pragma unroll
        for (int half = 0; half < 2; half++) {
            int m = m0 + warp_m * 32 + ma * 16 + g + half * 8;
            #pragma unroll
            for (int na = 0; na < 8; na++) {
                int o = o0 + warp_n * 64 + na * 8 + tg * 2;
                float2 v;
                v.x = acc[ma][na][half*2+0] + bias[o];
                v.y = acc[ma][na][half*2+1] + bias[o+1];
                *(float2*)&out[(size_t)m * DIMV + o] = v;
            }
        }
    }
}

// =====================================================================
extern "C" void kernel_launch(void* const* d_in, const int* in_sizes, int n_in,
                              void* d_out, int out_size) {
    const float* x      = (const float*)d_in[0];
    const float* Wqkv   = (const float*)d_in[1];
    const float* bqkv   = (const float*)d_in[2];
    const float* Wout   = (const float*)d_in[3];
    const float* bout   = (const float*)d_in[4];
    const float* relk   = (const float*)d_in[5];
    const float* relv   = (const float*)d_in[6];
    const float* alphas = (const float*)d_in[7];
    float* out = (float*)d_out;

    __half *xh, *xl, *wqh, *wql, *woh, *wol;
    cudaGetSymbolAddress((void**)&xh,  g_X16h);  cudaGetSymbolAddress((void**)&xl,  g_X16l);
    cudaGetSymbolAddress((void**)&wqh, g_Wq16h); cudaGetSymbolAddress((void**)&wql, g_Wq16l);
    cudaGetSymbolAddress((void**)&woh, g_Wo16h); cudaGetSymbolAddress((void**)&wol, g_Wo16l);

    k_split<<<(MQ * DIMV / 4 + 255) / 256, 256>>>(x, xh, xl, MQ * DIMV / 4);
    k_split<<<(CQKV * DIMV / 4 + 255) / 256, 256>>>(Wqkv, wqh, wql, CQKV * DIMV / 4);
    k_split<<<(DIMV * DIMV / 4 + 255) / 256, 256>>>(Wout, woh, wol, DIMV * DIMV / 4);

    cudaFuncSetAttribute(k_gemm_qkv, cudaFuncAttributeMaxDynamicSharedMemorySize, 4 * 128 * 72 * 2);
    k_gemm_qkv<<<dim3(24, 32), 256, 4 * 128 * 72 * 2>>>(bqkv);

    k_qr<<<ROWS / 32, 256>>>(relk);

    cudaFuncSetAttribute(k_scores, cudaFuncAttributeMaxDynamicSharedMemorySize, 4 * 128 * 72 * 2);
    k_scores<<<dim3(8, 8, BHH), 256, 4 * 128 * 72 * 2>>>();

    k_select<<<ROWS, 256>>>(relv);

    cudaFuncSetAttribute(k_apply, cudaFuncAttributeMaxDynamicSharedMemorySize, 163840);
    k_apply<<<BHH * 2, 512, 163840>>>(0, alphas);
    k_apply<<<BHH * 2, 512, 163840>>>(1, alphas);
    k_apply<<<BHH * 2, 512, 163840>>>(2, alphas);

    cudaFuncSetAttribute(k_gemm_out, cudaFuncAttributeMaxDynamicSharedMemorySize, 4 * 128 * 72 * 2);
    k_gemm_out<<<dim3(8, 32), 256, 4 * 128 * 72 * 2>>>(bout, out);
}

// round 14
// speedup vs baseline: 1.3226x; 1.1521x over previous
#include <cuda_runtime.h>
#include <cuda_fp16.h>

// ---------------- problem constants ----------------
#define Bb 4
#define NN 1024
#define DIMV 1024
#define HH 16
#define DHd 64
#define VOC 129            // 2*MAXREL+1
#define MAXREL 64
#define TOPKv 256
#define BHH (Bb*HH)        // 64
#define ROWS (BHH*NN)      // 65536
#define SCALEv 0.125f      // DH^-0.5
#define MQ (Bb*NN)         // 4096 token rows
#define CQKV (3*HH*DHd)    // 3072

typedef unsigned long long u64;

// ---------------- device scratch (no allocs allowed) ----------------
__device__ float g_Q[ROWS*DHd];
__device__ __half g_Q16h[ROWS*DHd];
__device__ __half g_Q16l[ROWS*DHd];
__device__ __half g_K16h[ROWS*DHd];
__device__ __half g_K16l[ROWS*DHd];
__device__ __half g_V16[ROWS*DHd];
__device__ float g_S[(size_t)ROWS*NN];        // 256 MB scores
__device__ float g_QR[ROWS*VOC];
__device__ float g_CW[ROWS*TOPKv];
__device__ int   g_CI[ROWS*TOPKv];
__device__ float g_ARel[ROWS*DHd];
__device__ __half g_VA16[ROWS*DHd];
__device__ __half g_VB16[ROWS*DHd];
__device__ float g_Res[ROWS*DHd];
// split planes for MMA GEMMs
__device__ __half g_X16h[MQ*DIMV],  g_X16l[MQ*DIMV];
__device__ __half g_Wq16h[CQKV*DIMV], g_Wq16l[CQKV*DIMV];
__device__ __half g_Wo16h[DIMV*DIMV], g_Wo16l[DIMV*DIMV];
__device__ __half g_R16h[MQ*DIMV],  g_R16l[MQ*DIMV];   // Res flat [m][dim]

// ---------------- packed f32x2 helpers ----------------
__device__ __forceinline__ void ffma2(u64 &d, u64 a, u64 b) {
    asm("fma.rn.f32x2 %0, %1, %2, %0;" : "+l"(d) : "l"(a), "l"(b));
}
__device__ __forceinline__ u64 dup2(float x) {
    u64 r; asm("mov.b64 %0, {%1, %1};" : "=l"(r) : "f"(x)); return r;
}
__device__ __forceinline__ float2 unpack2(u64 v) {
    float2 f; asm("mov.b64 {%0, %1}, %2;" : "=f"(f.x), "=f"(f.y) : "l"(v)); return f;
}
__device__ __forceinline__ unsigned smem_u32(const void* p) {
    unsigned a;
    asm("{ .reg .u64 t; cvta.to.shared.u64 t, %1; cvt.u32.u64 %0, t; }" : "=r"(a) : "l"(p));
    return a;
}
__device__ __forceinline__ void split16(float f, __half &h, __half &l) {
    h = __float2half_rn(f);
    l = __float2half_rn(f - __half2float(h));
}

// =====================================================================
// Kernel 0: split fp32 array -> fp16 hi/lo planes (vectorized)
// =====================================================================
__global__ void k_split(const float* __restrict__ src, __half* __restrict__ ph,
                        __half* __restrict__ pl, int n4) {
    int idx = blockIdx.x * blockDim.x + threadIdx.x;
    if (idx >= n4) return;
    float4 v = *(const float4*)&src[idx * 4];
    __half hh[4], hl[4];
    split16(v.x, hh[0], hl[0]);
    split16(v.y, hh[1], hl[1]);
    split16(v.z, hh[2], hl[2]);
    split16(v.w, hh[3], hl[3]);
    *(uint2*)&ph[idx * 4] = make_uint2(*(unsigned*)&hh[0], *(unsigned*)&hh[2]);
    *(uint2*)&pl[idx * 4] = make_uint2(*(unsigned*)&hl[0], *(unsigned*)&hl[2]);
}

// =====================================================================
// Kernel 1: qkv GEMM via split-fp16 MMA (acc = AhBh + AhBl + AlBh).
// 128x128 tile, BK=64 chunks x16, 8 warps 4(m)x2(n), 2 CTAs/SM.
// =====================================================================
__global__ __launch_bounds__(256, 2) void k_gemm_qkv(const float* __restrict__ bias) {
    extern __shared__ __half sdyn[];
    __half (*sAh)[72] = (__half(*)[72])(sdyn);
    __half (*sAl)[72] = (__half(*)[72])(sdyn + 128 * 72);
    __half (*sBh)[72] = (__half(*)[72])(sdyn + 2 * 128 * 72);
    __half (*sBl)[72] = (__half(*)[72])(sdyn + 3 * 128 * 72);
    int tid = threadIdx.x;
    int lane = tid & 31, wid = tid >> 5;
    int warp_m = wid & 3, warp_n = wid >> 2;
    int m0 = blockIdx.y * 128, c0 = blockIdx.x * 128;

    float acc[2][8][4];
    #pragma unroll
    for (int ma = 0; ma < 2; ma++)
        #pragma unroll
        for (int na = 0; na < 8; na++)
            #pragma unroll
            for (int q = 0; q < 4; q++) acc[ma][na][q] = 0.f;

    int lm = lane >> 3, lr = lane & 7;
    int aRowOff = (lm & 1) * 8 + lr;
    int aColOff = (lm >> 1) * 8;
    int bRowOff = (lm >> 1) * 8 + lr;
    int bColOff = (lm & 1) * 8;

    for (int kc = 0; kc < DIMV; kc += 64) {
        for (int e = tid; e < 1024; e += 256) {
            int r = e >> 3, s = (e & 7) * 8;
            *(uint4*)&sAh[r][s] = *(const uint4*)&g_X16h[(size_t)(m0 + r) * DIMV + kc + s];
            *(uint4*)&sAl[r][s] = *(const uint4*)&g_X16l[(size_t)(m0 + r) * DIMV + kc + s];
            *(uint4*)&sBh[r][s] = *(const uint4*)&g_Wq16h[(size_t)(c0 + r) * DIMV + kc + s];
            *(uint4*)&sBl[r][s] = *(const uint4*)&g_Wq16l[(size_t)(c0 + r) * DIMV + kc + s];
        }
        __syncthreads();
        #pragma unroll
        for (int kk = 0; kk < 4; kk++) {
            int kbase = kk * 16;
            unsigned ah[2][4], al[2][4];
            #pragma unroll
            for (int ma = 0; ma < 2; ma++) {
                int rowq = warp_m * 32 + ma * 16 + aRowOff;
                unsigned ad = smem_u32(&sAh[rowq][kbase + aColOff]);
                asm volatile("ldmatrix.sync.aligned.m8n8.x4.shared.b16 {%0,%1,%2,%3}, [%4];"
                             : "=r"(ah[ma][0]), "=r"(ah[ma][1]), "=r"(ah[ma][2]), "=r"(ah[ma][3]) : "r"(ad));
                ad = smem_u32(&sAl[rowq][kbase + aColOff]);
                asm volatile("ldmatrix.sync.aligned.m8n8.x4.shared.b16 {%0,%1,%2,%3}, [%4];"
                             : "=r"(al[ma][0]), "=r"(al[ma][1]), "=r"(al[ma][2]), "=r"(al[ma][3]) : "r"(ad));
            }
            unsigned bh_[8][2], bl_[8][2];
            #pragma unroll
            for (int np = 0; np < 4; np++) {
                int rowk = warp_n * 64 + np * 16 + bRowOff;
                unsigned r0, r1, r2, r3;
                unsigned ad = smem_u32(&sBh[rowk][kbase + bColOff]);
                asm volatile("ldmatrix.sync.aligned.m8n8.x4.shared.b16 {%0,%1,%2,%3}, [%4];"
                             : "=r"(r0), "=r"(r1), "=r"(r2), "=r"(r3) : "r"(ad));
                bh_[np*2+0][0] = r0; bh_[np*2+0][1] = r1;
                bh_[np*2+1][0] = r2; bh_[np*2+1][1] = r3;
                ad = smem_u32(&sBl[rowk][kbase + bColOff]);
                asm volatile("ldmatrix.sync.aligned.m8n8.x4.shared.b16 {%0,%1,%2,%3}, [%4];"
                             : "=r"(r0), "=r"(r1), "=r"(r2), "=r"(r3) : "r"(ad));
                bl_[np*2+0][0] = r0; bl_[np*2+0][1] = r1;
                bl_[np*2+1][0] = r2; bl_[np*2+1][1] = r3;
            }
            #pragma unroll
            for (int ma = 0; ma < 2; ma++) {
                #pragma unroll
                for (int na = 0; na < 8; na++) {
                    asm volatile("mma.sync.aligned.m16n8k16.row.col.f32.f16.f16.f32 "
                        "{%0,%1,%2,%3}, {%4,%5,%6,%7}, {%8,%9}, {%0,%1,%2,%3};"
                        : "+f"(acc[ma][na][0]), "+f"(acc[ma][na][1]), "+f"(acc[ma][na][2]), "+f"(acc[ma][na][3])
                        : "r"(ah[ma][0]), "r"(ah[ma][1]), "r"(ah[ma][2]), "r"(ah[ma][3]),
                          "r"(bh_[na][0]), "r"(bh_[na][1]));
                    asm volatile("mma.sync.aligned.m16n8k16.row.col.f32.f16.f16.f32 "
                        "{%0,%1,%2,%3}, {%4,%5,%6,%7}, {%8,%9}, {%0,%1,%2,%3};"
                        : "+f"(acc[ma][na][0]), "+f"(acc[ma][na][1]), "+f"(acc[ma][na][2]), "+f"(acc[ma][na][3])
                        : "r"(ah[ma][0]), "r"(ah[ma][1]), "r"(ah[ma][2]), "r"(ah[ma][3]),
                          "r"(bl_[na][0]), "r"(bl_[na][1]));
                    asm volatile("mma.sync.aligned.m16n8k16.row.col.f32.f16.f16.f32 "
                        "{%0,%1,%2,%3}, {%4,%5,%6,%7}, {%8,%9}, {%0,%1,%2,%3};"
                        : "+f"(acc[ma][na][0]), "+f"(acc[ma][na][1]), "+f"(acc[ma][na][2]), "+f"(acc[ma][na][3])
                        : "r"(al[ma][0]), "r"(al[ma][1]), "r"(al[ma][2]), "r"(al[ma][3]),
                          "r"(bh_[na][0]), "r"(bh_[na][1]));
                }
            }
        }
        __syncthreads();
    }

    // epilogue: bias + scatter
    int g = lane >> 2, tg = lane & 3;
    #pragma unroll
    for (int ma = 0; ma < 2; ma++) {
        #pragma unroll
        for (int half = 0; half < 2; half++) {
            int m = m0 + warp_m * 32 + ma * 16 + g + half * 8;
            int b = m >> 10, n = m & 1023;
            #pragma unroll
            for (int na = 0; na < 8; na++) {
                int c = c0 + warp_n * 64 + na * 8 + tg * 2;
                float2 v;
                v.x = acc[ma][na][half*2+0] + bias[c];
                v.y = acc[ma][na][half*2+1] + bias[c+1];
                int part = c >> 10;
                int hc = c & 1023;
                int h = hc >> 6, dh = hc & 63;
                size_t idx = ((size_t)((b * HH + h) * NN + n)) * DHd + dh;
                if (part == 2) {
                    __half2 hv = __floats2half2_rn(v.x, v.y);
                    *(unsigned*)&g_V16[idx] = *(unsigned*)&hv;
                } else {
                    __half h0, l0, h1, l1;
                    split16(v.x, h0, l0);
                    split16(v.y, h1, l1);
                    __half2 hp = __halves2half2(h0, h1);
                    __half2 lp = __halves2half2(l0, l1);
                    if (part == 0) {
                        *(float2*)&g_Q[idx] = v;
                        *(unsigned*)&g_Q16h[idx] = *(unsigned*)&hp;
                        *(unsigned*)&g_Q16l[idx] = *(unsigned*)&lp;
                    } else {
                        *(unsigned*)&g_K16h[idx] = *(unsigned*)&hp;
                        *(unsigned*)&g_K16l[idx] = *(unsigned*)&lp;
                    }
                }
            }
        }
    }
}

// =====================================================================
// Kernel 2: QR[row][t] = Q[row] . rel_k_emb[t]  (fp32, smem-staged)
// =====================================================================
__global__ __launch_bounds__(256) void k_qr(const float* __restrict__ relk) {
    __shared__ float sQ[32][68];
    __shared__ float srk[64][132];
    int tid = threadIdx.x;
    int row0 = blockIdx.x * 32;
    for (int e = tid; e < 32 * 64; e += 256) {
        int r = e >> 6, d = e & 63;
        sQ[r][d] = g_Q[(size_t)(row0 + r) * DHd + d];
    }
    for (int e = tid; e < 64 * 132; e += 256) {
        int d = e / 132, t = e % 132;
        srk[d][t] = (t < VOC) ? relk[t * DHd + d] : 0.f;
    }
    __syncthreads();
    for (int g = tid; g < 32 * 33; g += 256) {
        int r = g / 33, tt = g % 33;
        u64 a01 = 0, a23 = 0;
        #pragma unroll 16
        for (int d = 0; d < 64; d++) {
            u64 qd = dup2(sQ[r][d]);
            ulonglong2 f = *(const ulonglong2*)&srk[d][tt * 4];
            ffma2(a01, qd, f.x);
            ffma2(a23, qd, f.y);
        }
        float2 lo = unpack2(a01), hi = unpack2(a23);
        size_t base = (size_t)(row0 + r) * VOC;
        int t0 = tt * 4;
        if (tt < 32) {
            g_QR[base + t0 + 0] = lo.x;
            g_QR[base + t0 + 1] = lo.y;
            g_QR[base + t0 + 2] = hi.x;
            g_QR[base + t0 + 3] = hi.y;
        } else {
            g_QR[base + 128] = lo.x;
        }
    }
}

// =====================================================================
// Kernel 3: S = SCALE*(Q.K^T) + QR gather via split-fp16 MMA.
// grid (8, 8, 64), 256 threads, 2 CTAs/SM.
// =====================================================================
__global__ __launch_bounds__(256, 2) void k_scores() {
    extern __shared__ __half sdyn[];
    __half (*sQh)[72] = (__half(*)[72])(sdyn);
    __half (*sQl)[72] = (__half(*)[72])(sdyn + 128 * 72);
    __half (*sKh)[72] = (__half(*)[72])(sdyn + 2 * 128 * 72);
    __half (*sKl)[72] = (__half(*)[72])(sdyn + 3 * 128 * 72);
    int tid = threadIdx.x;
    int lane = tid & 31, wid = tid >> 5;
    int warp_m = wid & 3;
    int warp_n = wid >> 2;
    int bh = blockIdx.z;
    int i0 = blockIdx.y * 128, j0 = blockIdx.x * 128;

    {
        const __half* gqh = g_Q16h + (size_t)(bh * NN + i0) * DHd;
        const __half* gql = g_Q16l + (size_t)(bh * NN + i0) * DHd;
        const __half* gkh = g_K16h + (size_t)(bh * NN + j0) * DHd;
        const __half* gkl = g_K16l + (size_t)(bh * NN + j0) * DHd;
        for (int e = tid; e < 1024; e += 256) {
            int r = e >> 3, s = (e & 7) * 8;
            *(uint4*)&sQh[r][s] = *(const uint4*)&gqh[r * DHd + s];
            *(uint4*)&sQl[r][s] = *(const uint4*)&gql[r * DHd + s];
            *(uint4*)&sKh[r][s] = *(const uint4*)&gkh[r * DHd + s];
            *(uint4*)&sKl[r][s] = *(const uint4*)&gkl[r * DHd + s];
        }
    }
    __syncthreads();

    float acc[2][8][4];
    #pragma unroll
    for (int ma = 0; ma < 2; ma++)
        #pragma unroll
        for (int na = 0; na < 8; na++)
            #pragma unroll
            for (int q = 0; q < 4; q++) acc[ma][na][q] = 0.f;

    int lm = lane >> 3;
    int lr = lane & 7;
    int aRowOff = (lm & 1) * 8 + lr;
    int aColOff = (lm >> 1) * 8;
    int bRowOff = (lm >> 1) * 8 + lr;
    int bColOff = (lm & 1) * 8;

    #pragma unroll
    for (int kk = 0; kk < 4; kk++) {
        int kbase = kk * 16;
        unsigned ah[2][4], al[2][4];
        #pragma unroll
        for (int ma = 0; ma < 2; ma++) {
            int rowq = warp_m * 32 + ma * 16 + aRowOff;
            unsigned addrh = smem_u32(&sQh[rowq][kbase + aColOff]);
            asm volatile("ldmatrix.sync.aligned.m8n8.x4.shared.b16 {%0,%1,%2,%3}, [%4];"
                         : "=r"(ah[ma][0]), "=r"(ah[ma][1]), "=r"(ah[ma][2]), "=r"(ah[ma][3])
                         : "r"(addrh));
            unsigned addrl = smem_u32(&sQl[rowq][kbase + aColOff]);
            asm volatile("ldmatrix.sync.aligned.m8n8.x4.shared.b16 {%0,%1,%2,%3}, [%4];"
                         : "=r"(al[ma][0]), "=r"(al[ma][1]), "=r"(al[ma][2]), "=r"(al[ma][3])
                         : "r"(addrl));
        }
        unsigned bh_[8][2], bl_[8][2];
        #pragma unroll
        for (int np = 0; np < 4; np++) {
            int rowk = warp_n * 64 + np * 16 + bRowOff;
            unsigned r0, r1, r2, r3;
            unsigned addrh = smem_u32(&sKh[rowk][kbase + bColOff]);
            asm volatile("ldmatrix.sync.aligned.m8n8.x4.shared.b16 {%0,%1,%2,%3}, [%4];"
                         : "=r"(r0), "=r"(r1), "=r"(r2), "=r"(r3) : "r"(addrh));
            bh_[np*2+0][0] = r0; bh_[np*2+0][1] = r1;
            bh_[np*2+1][0] = r2; bh_[np*2+1][1] = r3;
            unsigned addrl = smem_u32(&sKl[rowk][kbase + bColOff]);
            asm volatile("ldmatrix.sync.aligned.m8n8.x4.shared.b16 {%0,%1,%2,%3}, [%4];"
                         : "=r"(r0), "=r"(r1), "=r"(r2), "=r"(r3) : "r"(addrl));
            bl_[np*2+0][0] = r0; bl_[np*2+0][1] = r1;
            bl_[np*2+1][0] = r2; bl_[np*2+1][1] = r3;
        }
        #pragma unroll
        for (int ma = 0; ma < 2; ma++) {
            #pragma unroll
            for (int na = 0; na < 8; na++) {
                asm volatile("mma.sync.aligned.m16n8k16.row.col.f32.f16.f16.f32 "
                    "{%0,%1,%2,%3}, {%4,%5,%6,%7}, {%8,%9}, {%0,%1,%2,%3};"
                    : "+f"(acc[ma][na][0]), "+f"(acc[ma][na][1]), "+f"(acc[ma][na][2]), "+f"(acc[ma][na][3])
                    : "r"(ah[ma][0]), "r"(ah[ma][1]), "r"(ah[ma][2]), "r"(ah[ma][3]),
                      "r"(bh_[na][0]), "r"(bh_[na][1]));
                asm volatile("mma.sync.aligned.m16n8k16.row.col.f32.f16.f16.f32 "
                    "{%0,%1,%2,%3}, {%4,%5,%6,%7}, {%8,%9}, {%0,%1,%2,%3};"
                    : "+f"(acc[ma][na][0]), "+f"(acc[ma][na][1]), "+f"(acc[ma][na][2]), "+f"(acc[ma][na][3])
                    : "r"(ah[ma][0]), "r"(ah[ma][1]), "r"(ah[ma][2]), "r"(ah[ma][3]),
                      "r"(bl_[na][0]), "r"(bl_[na][1]));
                asm volatile("mma.sync.aligned.m16n8k16.row.col.f32.f16.f16.f32 "
                    "{%0,%1,%2,%3}, {%4,%5,%6,%7}, {%8,%9}, {%0,%1,%2,%3};"
                    : "+f"(acc[ma][na][0]), "+f"(acc[ma][na][1]), "+f"(acc[ma][na][2]), "+f"(acc[ma][na][3])
                    : "r"(al[ma][0]), "r"(al[ma][1]), "r"(al[ma][2]), "r"(al[ma][3]),
                      "r"(bh_[na][0]), "r"(bh_[na][1]));
            }
        }
    }

    int g = lane >> 2, tg = lane & 3;
    #pragma unroll
    for (int ma = 0; ma < 2; ma++) {
        int rowA = i0 + warp_m * 32 + ma * 16 + g;
        #pragma unroll
        for (int half = 0; half < 2; half++) {
            int ii = rowA + half * 8;
            const float* qr = &g_QR[(size_t)(bh * NN + ii) * VOC];
            size_t sbase = ((size_t)(bh * NN + ii)) * NN;
            #pragma unroll
            for (int na = 0; na < 8; na++) {
                int jj = j0 + warp_n * 64 + na * 8 + tg * 2;
                int d0 = ii - jj;
                d0 = d0 < -MAXREL ? -MAXREL : (d0 > MAXREL ? MAXREL : d0);
                int d1 = ii - (jj + 1);
                d1 = d1 < -MAXREL ? -MAXREL : (d1 > MAXREL ? MAXREL : d1);
                float2 v;
                v.x = acc[ma][na][half*2+0] * SCALEv + qr[d0 + MAXREL];
                v.y = acc[ma][na][half*2+1] * SCALEv + qr[d1 + MAXREL];
                *(float2*)&g_S[sbase + jj] = v;
            }
        }
    }
}

// float -> order-preserving uint key
__device__ __forceinline__ unsigned ftokey(float f) {
    unsigned u = __float_as_uint(f);
    return (u & 0x80000000u) ? ~u : (u | 0x80000000u);
}

// =====================================================================
// Kernel 4 (fused): radix-select + masked softmax + compaction + ARel.
// (proven form, float4 row load) One block (256 threads) per score row.
// =====================================================================
__global__ __launch_bounds__(256) void k_select(const float* __restrict__ relv) {
    __shared__ float sbuf[1024];
    __shared__ int   hist[256];
    __shared__ float wredf[8];
    __shared__ float wredf2[8];
    __shared__ int   wredi[8];
    __shared__ float rbin[VOC];
    __shared__ unsigned sh_selb;
    __shared__ int      sh_rem;

    int row = blockIdx.x;
    int tid = threadIdx.x;
    int lane = tid & 31, wid = tid >> 5;
    int i = row & (NN - 1);
    const float* src = &g_S[(size_t)row * NN];

    float4 lv4 = *(const float4*)&src[tid * 4];
    float lv[4] = {lv4.x, lv4.y, lv4.z, lv4.w};
    unsigned kv[4];
    #pragma unroll
    for (int r = 0; r < 4; r++) kv[r] = ftokey(lv[r]);

    float m = fmaxf(fmaxf(lv[0], lv[1]), fmaxf(lv[2], lv[3]));
    #pragma unroll
    for (int off = 16; off > 0; off >>= 1)
        m = fmaxf(m, __shfl_xor_sync(0xffffffffu, m, off));
    if (lane == 0) wredf[wid] = m;
    __syncthreads();
    float rmax = wredf[0];
    #pragma unroll
    for (int w = 1; w < 8; w++) rmax = fmaxf(rmax, wredf[w]);

    unsigned prefix = 0;
    int need = TOPKv;
    for (int round = 3; round >= 0; round--) {
        hist[tid] = 0;
        __syncthreads();
        unsigned mask = (round == 3) ? 0u : (0xFFFFFFFFu << ((round + 1) * 8));
        #pragma unroll
        for (int r = 0; r < 4; r++) {
            if ((kv[r] & mask) == prefix)
                atomicAdd(&hist[(kv[r] >> (round * 8)) & 255], 1);
        }
        __syncthreads();
        int h = hist[tid];
        int s = h;
        #pragma unroll
        for (int off = 1; off < 32; off <<= 1) {
            int v = __shfl_down_sync(0xffffffffu, s, off);
            if (lane + off < 32) s += v;
        }
        int wtot = __shfl_sync(0xffffffffu, s, 0);
        if (lane == 0) wredi[wid] = wtot;
        __syncthreads();
        int tail = 0;
        #pragma unroll
        for (int w = 0; w < 8; w++) if (w > wid) tail += wredi[w];
        int Sb = s + tail;
        int Sb1 = Sb - h;
        if (Sb >= need && Sb1 < need) { sh_selb = (unsigned)tid; sh_rem = Sb1; }
        __syncthreads();
        prefix |= sh_selb << (round * 8);
        need -= sh_rem;
        __syncthreads();
    }
    unsigned thrkey = prefix;

    float lsum = 0.f;
    #pragma unroll
    for (int r = 0; r < 4; r++) {
        int j = tid * 4 + r;
        float e;
        if (kv[r] >= thrkey) { e = __expf(lv[r] - rmax); lsum += e; }
        else e = -1.0f;
        sbuf[j] = e;
    }
    float ws = lsum;
    #pragma unroll
    for (int off = 16; off > 0; off >>= 1)
        ws += __shfl_xor_sync(0xffffffffu, ws, off);
    if (lane == 0) wredf[wid] = ws;
    __syncthreads();
    float tot = 0.f;
    #pragma unroll
    for (int w = 0; w < 8; w++) tot += wredf[w];
    float inv = 1.0f / tot;

    if (tid >= 1 && tid < 128) {
        int j = i + MAXREL - tid;
        float v = 0.f;
        if (j >= 0 && j < NN) {
            float e = sbuf[j];
            if (e >= 0.f) v = e * inv;
        }
        rbin[tid] = v;
    }
    float s0 = 0.f, s128 = 0.f;
    #pragma unroll
    for (int r = 0; r < 4; r++) {
        int j = tid * 4 + r;
        float e = sbuf[j];
        float a = (e >= 0.f) ? e * inv : 0.f;
        if (j >= i + MAXREL) s0 += a;
        if (j <= i - MAXREL) s128 += a;
    }
    #pragma unroll
    for (int off = 16; off > 0; off >>= 1) {
        s0   += __shfl_xor_sync(0xffffffffu, s0, off);
        s128 += __shfl_xor_sync(0xffffffffu, s128, off);
    }
    __syncthreads();
    if (lane == 0) { wredf[wid] = s0; wredf2[wid] = s128; }
    __syncthreads();
    if (tid == 0) {
        float a = 0.f, b = 0.f;
        #pragma unroll
        for (int w = 0; w < 8; w++) { a += wredf[w]; b += wredf2[w]; }
        rbin[0] = a; rbin[MAXREL * 2] = b;
    }
    __syncthreads();

    if (tid < DHd) {
        float acc = 0.f;
        #pragma unroll
        for (int t = 0; t < VOC; t++) acc += rbin[t] * __ldg(&relv[t * DHd + tid]);
        g_ARel[(size_t)row * DHd + tid] = acc;
    }

    int kc = 0;
    #pragma unroll
    for (int r = 0; r < 4; r++) if (sbuf[tid * 4 + r] >= 0.f) kc++;
    int p = kc;
    #pragma unroll
    for (int off = 1; off < 32; off <<= 1) {
        int v = __shfl_up_sync(0xffffffffu, p, off);
        if (lane >= off) p += v;
    }
    if (lane == 31) wredi[wid] = p;
    __syncthreads();
    int base = 0;
    #pragma unroll
    for (int w = 0; w < 8; w++) if (w < wid) base += wredi[w];
    int pos = base + p - kc;
    size_t cbase = (size_t)row * TOPKv;
    #pragma unroll
    for (int r = 0; r < 4; r++) {
        int j = tid * 4 + r;
        float e = sbuf[j];
        if (e >= 0.f) {
            if (pos < TOPKv) { g_CI[cbase + pos] = j; g_CW[cbase + pos] = e * inv; }
            pos++;
        }
    }
}

// =====================================================================
// Kernel 5: sparse apply with fp16 V (proven). ord==2 additionally emits
// Res in FLAT [m][dim] layout as fp16 hi/lo for the MMA out-GEMM.
// grid (bh, row-half) = 128 blocks, 512 threads.
// =====================================================================
__global__ __launch_bounds__(512) void k_apply(int ord, const float* __restrict__ alphas_raw) {
    extern __shared__ char smemc[];
    unsigned* sVu = (unsigned*)smemc;
    float2*   sIW = (float2*)(smemc + 1024 * 32 * 4);

    const __half* Vin16  = (ord == 0) ? g_V16  : ((ord == 1) ? g_VA16 : g_VB16);
    __half*       Vout16 = (ord == 0) ? g_VA16 : ((ord == 1) ? g_VB16 : g_VA16);

    int bh = blockIdx.x >> 1;
    int rh = blockIdx.x & 1;
    int tid = threadIdx.x, wid = tid >> 5, lane = tid & 31;

    {
        const uint4* srcv = (const uint4*)(Vin16 + (size_t)bh * NN * DHd);
        uint4* dstv = (uint4*)sVu;
        for (int e = tid; e < 8192; e += 512) dstv[e] = srcv[e];
    }
    __syncthreads();

    int h = bh & (HH - 1);
    int bb = bh >> 4;
    float araw = alphas_raw[ord * HH + h];
    float alpha = 1.0f / (1.0f + __expf(-araw));
    float2* myIW = sIW + wid * 256;

    for (int i = rh * 512 + wid; i < rh * 512 + 512; i += 16) {
        int row = bh * NN + i;
        const int*   ci = &g_CI[(size_t)row * TOPKv];
        const float* cw = &g_CW[(size_t)row * TOPKv];
        #pragma unroll
        for (int q = 0; q < 8; q++) {
            int p = q * 32 + lane;
            myIW[p] = make_float2(cw[p], __int_as_float(ci[p]));
        }
        __syncwarp();
        float2 a0 = {0.f, 0.f}, a1 = {0.f, 0.f}, a2 = {0.f, 0.f}, a3 = {0.f, 0.f};
        #pragma unroll 4
        for (int p = 0; p < TOPKv; p += 4) {
            float2 w0 = myIW[p+0], w1 = myIW[p+1], w2 = myIW[p+2], w3 = myIW[p+3];
            unsigned u0 = sVu[__float_as_int(w0.y) * 32 + lane];
            unsigned u1 = sVu[__float_as_int(w1.y) * 32 + lane];
            unsigned u2 = sVu[__float_as_int(w2.y) * 32 + lane];
            unsigned u3 = sVu[__float_as_int(w3.y) * 32 + lane];
            float2 v0 = __half22float2(*(__half2*)&u0);
            float2 v1 = __half22float2(*(__half2*)&u1);
            float2 v2 = __half22float2(*(__half2*)&u2);
            float2 v3 = __half22float2(*(__half2*)&u3);
            a0.x += w0.x * v0.x; a0.y += w0.x * v0.y;
            a1.x += w1.x * v1.x; a1.y += w1.x * v1.y;
            a2.x += w2.x * v2.x; a2.y += w2.x * v2.y;
            a3.x += w3.x * v3.x; a3.y += w3.x * v3.y;
        }
        float2 acc;
        acc.x = (a0.x + a1.x) + (a2.x + a3.x);
        acc.y = (a0.y + a1.y) + (a2.y + a3.y);
        __syncwarp();

        size_t oidx = (size_t)row * DHd + 2 * lane;
        if (ord == 0) {
            float2 ar = *(const float2*)&g_ARel[oidx];
            acc.x += ar.x; acc.y += ar.y;
        }
        __half2 hv = __floats2half2_rn(acc.x, acc.y);
        *(unsigned*)&Vout16[oidx] = *(unsigned*)&hv;
        if (ord == 0) {
            float2 rv = make_float2(alpha * acc.x, alpha * acc.y);
            *(float2*)&g_Res[oidx] = rv;
        } else if (ord == 1) {
            float2 pr = *(float2*)&g_Res[oidx];
            pr.x += alpha * acc.x;
            pr.y += alpha * acc.y;
            *(float2*)&g_Res[oidx] = pr;
        } else {
            float2 pr = *(float2*)&g_Res[oidx];
            pr.x += alpha * acc.x;
            pr.y += alpha * acc.y;
            size_t fidx = ((size_t)(bb * 1024 + i)) * DIMV + h * DHd + 2 * lane;
            __half h0, l0, h1, l1;
            split16(pr.x, h0, l0);
            split16(pr.y, h1, l1);
            __half2 hp = __halves2half2(h0, h1);
            __half2 lp = __halves2half2(l0, l1);
            *(unsigned*)&g_R16h[fidx] = *(unsigned*)&hp;
            *(unsigned*)&g_R16l[fidx] = *(unsigned*)&lp;
        }
    }
}

// =====================================================================
// Kernel 6: out = Res_flat @ Wout^T + bout via split-fp16 MMA, 2 CTAs/SM.
// grid (8, 32), 256 threads.
// =====================================================================
__global__ __launch_bounds__(256, 2) void k_gemm_out(const float* __restrict__ bias,
                                                     float* __restrict__ out) {
    extern __shared__ __half sdyn[];
    __half (*sAh)[72] = (__half(*)[72])(sdyn);
    __half (*sAl)[72] = (__half(*)[72])(sdyn + 128 * 72);
    __half (*sBh)[72] = (__half(*)[72])(sdyn + 2 * 128 * 72);
    __half (*sBl)[72] = (__half(*)[72])(sdyn + 3 * 128 * 72);
    int tid = threadIdx.x;
    int lane = tid & 31, wid = tid >> 5;
    int warp_m = wid & 3, warp_n = wid >> 2;
    int m0 = blockIdx.y * 128, o0 = blockIdx.x * 128;

    float acc[2][8][4];
    #pragma unroll
    for (int ma = 0; ma < 2; ma++)
        #pragma unroll
        for (int na = 0; na < 8; na++)
            #pragma unroll
            for (int q = 0; q < 4; q++) acc[ma][na][q] = 0.f;

    int lm = lane >> 3, lr = lane & 7;
    int aRowOff = (lm & 1) * 8 + lr;
    int aColOff = (lm >> 1) * 8;
    int bRowOff = (lm >> 1) * 8 + lr;
    int bColOff = (lm & 1) * 8;

    for (int kc = 0; kc < DIMV; kc += 64) {
        for (int e = tid; e < 1024; e += 256) {
            int r = e >> 3, s = (e & 7) * 8;
            *(uint4*)&sAh[r][s] = *(const uint4*)&g_R16h[(size_t)(m0 + r) * DIMV + kc + s];
            *(uint4*)&sAl[r][s] = *(const uint4*)&g_R16l[(size_t)(m0 + r) * DIMV + kc + s];
            *(uint4*)&sBh[r][s] = *(const uint4*)&g_Wo16h[(size_t)(o0 + r) * DIMV + kc + s];
            *(uint4*)&sBl[r][s] = *(const uint4*)&g_Wo16l[(size_t)(o0 + r) * DIMV + kc + s];
        }
        __syncthreads();
        #pragma unroll
        for (int kk = 0; kk < 4; kk++) {
            int kbase = kk * 16;
            unsigned ah[2][4], al[2][4];
            #pragma unroll
            for (int ma = 0; ma < 2; ma++) {
                int rowq = warp_m * 32 + ma * 16 + aRowOff;
                unsigned ad = smem_u32(&sAh[rowq][kbase + aColOff]);
                asm volatile("ldmatrix.sync.aligned.m8n8.x4.shared.b16 {%0,%1,%2,%3}, [%4];"
                             : "=r"(ah[ma][0]), "=r"(ah[ma][1]), "=r"(ah[ma][2]), "=r"(ah[ma][3]) : "r"(ad));
                ad = smem_u32(&sAl[rowq][kbase + aColOff]);
                asm volatile("ldmatrix.sync.aligned.m8n8.x4.shared.b16 {%0,%1,%2,%3}, [%4];"
                             : "=r"(al[ma][0]), "=r"(al[ma][1]), "=r"(al[ma][2]), "=r"(al[ma][3]) : "r"(ad));
            }
            unsigned bh_[8][2], bl_[8][2];
            #pragma unroll
            for (int np = 0; np < 4; np++) {
                int rowk = warp_n * 64 + np * 16 + bRowOff;
                unsigned r0, r1, r2, r3;
                unsigned ad = smem_u32(&sBh[rowk][kbase + bColOff]);
                asm volatile("ldmatrix.sync.aligned.m8n8.x4.shared.b16 {%0,%1,%2,%3}, [%4];"
                             : "=r"(r0), "=r"(r1), "=r"(r2), "=r"(r3) : "r"(ad));
                bh_[np*2+0][0] = r0; bh_[np*2+0][1] = r1;
                bh_[np*2+1][0] = r2; bh_[np*2+1][1] = r3;
                ad = smem_u32(&sBl[rowk][kbase + bColOff]);
                asm volatile("ldmatrix.sync.aligned.m8n8.x4.shared.b16 {%0,%1,%2,%3}, [%4];"
                             : "=r"(r0), "=r"(r1), "=r"(r2), "=r"(r3) : "r"(ad));
                bl_[np*2+0][0] = r0; bl_[np*2+0][1] = r1;
                bl_[np*2+1][0] = r2; bl_[np*2+1][1] = r3;
            }
            #pragma unroll
            for (int ma = 0; ma < 2; ma++) {
                #pragma unroll
                for (int na = 0; na < 8; na++) {
                    asm volatile("mma.sync.aligned.m16n8k16.row.col.f32.f16.f16.f32 "
                        "{%0,%1,%2,%3}, {%4,%5,%6,%7}, {%8,%9}, {%0,%1,%2,%3};"
                        : "+f"(acc[ma][na][0]), "+f"(acc[ma][na][1]), "+f"(acc[ma][na][2]), "+f"(acc[ma][na][3])
                        : "r"(ah[ma][0]), "r"(ah[ma][1]), "r"(ah[ma][2]), "r"(ah[ma][3]),
                          "r"(bh_[na][0]), "r"(bh_[na][1]));
                    asm volatile("mma.sync.aligned.m16n8k16.row.col.f32.f16.f16.f32 "
                        "{%0,%1,%2,%3}, {%4,%5,%6,%7}, {%8,%9}, {%0,%1,%2,%3};"
                        : "+f"(acc[ma][na][0]), "+f"(acc[ma][na][1]), "+f"(acc[ma][na][2]), "+f"(acc[ma][na][3])
                        : "r"(ah[ma][0]), "r"(ah[ma][1]), "r"(ah[ma][2]), "r"(ah[ma][3]),
                          "r"(bl_[na][0]), "r"(bl_[na][1]));
                    asm volatile("mma.sync.aligned.m16n8k16.row.col.f32.f16.f16.f32 "
                        "{%0,%1,%2,%3}, {%4,%5,%6,%7}, {%8,%9}, {%0,%1,%2,%3};"
                        : "+f"(acc[ma][na][0]), "+f"(acc[ma][na][1]), "+f"(acc[ma][na][2]), "+f"(acc[ma][na][3])
                        : "r"(al[ma][0]), "r"(al[ma][1]), "r"(al[ma][2]), "r"(al[ma][3]),
                          "r"(bh_[na][0]), "r"(bh_[na][1]));
                }
            }
        }
        __syncthreads();
    }

    int g = lane >> 2, tg = lane & 3;
    #pragma unroll
    for (int ma = 0; ma < 2; ma++) {
        #pragma unroll
        for (int half = 0; half < 2; half++) {
            int m = m0 + warp_m * 32 + ma * 16 + g + half * 8;
            #pragma unroll
            for (int na = 0; na < 8; na++) {
                int o = o0 + warp_n * 64 + na * 8 + tg * 2;
                float2 v;
                v.x = acc[ma][na][half*2+0] + bias[o];
                v.y = acc[ma][na][half*2+1] + bias[o+1];
                *(float2*)&out[(size_t)m * DIMV + o] = v;
            }
        }
    }
}

// =====================================================================
extern "C" void kernel_launch(void* const* d_in, const int* in_sizes, int n_in,
                              void* d_out, int out_size) {
    const float* x      = (const float*)d_in[0];
    const float* Wqkv   = (const float*)d_in[1];
    const float* bqkv   = (const float*)d_in[2];
    const float* Wout   = (const float*)d_in[3];
    const float* bout   = (const float*)d_in[4];
    const float* relk   = (const float*)d_in[5];
    const float* relv   = (const float*)d_in[6];
    const float* alphas = (const float*)d_in[7];
    float* out = (float*)d_out;

    __half *xh, *xl, *wqh, *wql, *woh, *wol;
    cudaGetSymbolAddress((void**)&xh,  g_X16h);  cudaGetSymbolAddress((void**)&xl,  g_X16l);
    cudaGetSymbolAddress((void**)&wqh, g_Wq16h); cudaGetSymbolAddress((void**)&wql, g_Wq16l);
    cudaGetSymbolAddress((void**)&woh, g_Wo16h); cudaGetSymbolAddress((void**)&wol, g_Wo16l);

    k_split<<<(MQ * DIMV / 4 + 255) / 256, 256>>>(x, xh, xl, MQ * DIMV / 4);
    k_split<<<(CQKV * DIMV / 4 + 255) / 256, 256>>>(Wqkv, wqh, wql, CQKV * DIMV / 4);
    k_split<<<(DIMV * DIMV / 4 + 255) / 256, 256>>>(Wout, woh, wol, DIMV * DIMV / 4);

    cudaFuncSetAttribute(k_gemm_qkv, cudaFuncAttributeMaxDynamicSharedMemorySize, 4 * 128 * 72 * 2);
    k_gemm_qkv<<<dim3(24, 32), 256, 4 * 128 * 72 * 2>>>(bqkv);

    k_qr<<<ROWS / 32, 256>>>(relk);

    cudaFuncSetAttribute(k_scores, cudaFuncAttributeMaxDynamicSharedMemorySize, 4 * 128 * 72 * 2);
    k_scores<<<dim3(8, 8, BHH), 256, 4 * 128 * 72 * 2>>>();

    k_select<<<ROWS, 256>>>(relv);

    cudaFuncSetAttribute(k_apply, cudaFuncAttributeMaxDynamicSharedMemorySize, 163840);
    k_apply<<<BHH * 2, 512, 163840>>>(0, alphas);
    k_apply<<<BHH * 2, 512, 163840>>>(1, alphas);
    k_apply<<<BHH * 2, 512, 163840>>>(2, alphas);

    cudaFuncSetAttribute(k_gemm_out, cudaFuncAttributeMaxDynamicSharedMemorySize, 4 * 128 * 72 * 2);
    k_gemm_out<<<dim3(8, 32), 256, 4 * 128 * 72 * 2>>>(bout, out);
}

// round 15
// speedup vs baseline: 1.3467x; 1.0182x over previous
#include <cuda_runtime.h>
#include <cuda_fp16.h>

// ---------------- problem constants ----------------
#define Bb 4
#define NN 1024
#define DIMV 1024
#define HH 16
#define DHd 64
#define VOC 129            // 2*MAXREL+1
#define MAXREL 64
#define TOPKv 256
#define BHH (Bb*HH)        // 64
#define ROWS (BHH*NN)      // 65536
#define SCALEv 0.125f      // DH^-0.5
#define MQ (Bb*NN)         // 4096 token rows
#define CQKV (3*HH*DHd)    // 3072

typedef unsigned long long u64;

// ---------------- device scratch (no allocs allowed) ----------------
__device__ float g_Q[ROWS*DHd];
__device__ __half g_Q16h[ROWS*DHd];
__device__ __half g_Q16l[ROWS*DHd];
__device__ __half g_K16h[ROWS*DHd];
__device__ __half g_K16l[ROWS*DHd];
__device__ __half g_V16[ROWS*DHd];
__device__ float g_S[(size_t)ROWS*NN];        // 256 MB scores
__device__ float g_QR[ROWS*VOC];
__device__ float g_CW[ROWS*TOPKv];
__device__ int   g_CI[ROWS*TOPKv];
__device__ float g_ARel[ROWS*DHd];
__device__ __half g_VA16[ROWS*DHd];
__device__ __half g_VB16[ROWS*DHd];
__device__ float g_Res[ROWS*DHd];
// split planes for MMA GEMMs
__device__ __half g_X16h[MQ*DIMV],  g_X16l[MQ*DIMV];
__device__ __half g_Wq16h[CQKV*DIMV], g_Wq16l[CQKV*DIMV];
__device__ __half g_Wo16h[DIMV*DIMV], g_Wo16l[DIMV*DIMV];
__device__ __half g_R16h[MQ*DIMV],  g_R16l[MQ*DIMV];   // Res flat [m][dim]

// ---------------- helpers ----------------
__device__ __forceinline__ void ffma2(u64 &d, u64 a, u64 b) {
    asm("fma.rn.f32x2 %0, %1, %2, %0;" : "+l"(d) : "l"(a), "l"(b));
}
__device__ __forceinline__ u64 dup2(float x) {
    u64 r; asm("mov.b64 %0, {%1, %1};" : "=l"(r) : "f"(x)); return r;
}
__device__ __forceinline__ float2 unpack2(u64 v) {
    float2 f; asm("mov.b64 {%0, %1}, %2;" : "=f"(f.x), "=f"(f.y) : "l"(v)); return f;
}
__device__ __forceinline__ unsigned smem_u32(const void* p) {
    unsigned a;
    asm("{ .reg .u64 t; cvta.to.shared.u64 t, %1; cvt.u32.u64 %0, t; }" : "=r"(a) : "l"(p));
    return a;
}
__device__ __forceinline__ void split16(float f, __half &h, __half &l) {
    h = __float2half_rn(f);
    l = __float2half_rn(f - __half2float(h));
}
__device__ __forceinline__ void cp16(unsigned dst, const void* src) {
    asm volatile("cp.async.cg.shared.global [%0], [%1], 16;" :: "r"(dst), "l"(src));
}
__device__ __forceinline__ void cp_commit_wait() {
    asm volatile("cp.async.commit_group;" ::: "memory");
    asm volatile("cp.async.wait_group 0;" ::: "memory");
}

// =====================================================================
// Kernel 0: split fp32 array -> fp16 hi/lo planes (vectorized)
// =====================================================================
__global__ void k_split(const float* __restrict__ src, __half* __restrict__ ph,
                        __half* __restrict__ pl, int n4) {
    int idx = blockIdx.x * blockDim.x + threadIdx.x;
    if (idx >= n4) return;
    float4 v = *(const float4*)&src[idx * 4];
    __half hh[4], hl[4];
    split16(v.x, hh[0], hl[0]);
    split16(v.y, hh[1], hl[1]);
    split16(v.z, hh[2], hl[2]);
    split16(v.w, hh[3], hl[3]);
    *(uint2*)&ph[idx * 4] = make_uint2(*(unsigned*)&hh[0], *(unsigned*)&hh[2]);
    *(uint2*)&pl[idx * 4] = make_uint2(*(unsigned*)&hl[0], *(unsigned*)&hl[2]);
}

// =====================================================================
// Kernel 1: qkv GEMM via split-fp16 MMA (acc = AhBh + AhBl + AlBh).
// 128x128 tile, BK=64 chunks, 8 warps 4(m)x2(n), 2 CTAs/SM, cp.async.
// =====================================================================
__global__ __launch_bounds__(256, 2) void k_gemm_qkv(const float* __restrict__ bias) {
    extern __shared__ __half sdyn[];
    __half (*sAh)[72] = (__half(*)[72])(sdyn);
    __half (*sAl)[72] = (__half(*)[72])(sdyn + 128 * 72);
    __half (*sBh)[72] = (__half(*)[72])(sdyn + 2 * 128 * 72);
    __half (*sBl)[72] = (__half(*)[72])(sdyn + 3 * 128 * 72);
    int tid = threadIdx.x;
    int lane = tid & 31, wid = tid >> 5;
    int warp_m = wid & 3, warp_n = wid >> 2;
    int m0 = blockIdx.y * 128, c0 = blockIdx.x * 128;

    float acc[2][8][4];
    #pragma unroll
    for (int ma = 0; ma < 2; ma++)
        #pragma unroll
        for (int na = 0; na < 8; na++)
            #pragma unroll
            for (int q = 0; q < 4; q++) acc[ma][na][q] = 0.f;

    int lm = lane >> 3, lr = lane & 7;
    int aRowOff = (lm & 1) * 8 + lr;
    int aColOff = (lm >> 1) * 8;
    int bRowOff = (lm >> 1) * 8 + lr;
    int bColOff = (lm & 1) * 8;

    for (int kc = 0; kc < DIMV; kc += 64) {
        for (int e = tid; e < 1024; e += 256) {
            int r = e >> 3, s = (e & 7) * 8;
            cp16(smem_u32(&sAh[r][s]), &g_X16h[(size_t)(m0 + r) * DIMV + kc + s]);
            cp16(smem_u32(&sAl[r][s]), &g_X16l[(size_t)(m0 + r) * DIMV + kc + s]);
            cp16(smem_u32(&sBh[r][s]), &g_Wq16h[(size_t)(c0 + r) * DIMV + kc + s]);
            cp16(smem_u32(&sBl[r][s]), &g_Wq16l[(size_t)(c0 + r) * DIMV + kc + s]);
        }
        cp_commit_wait();
        __syncthreads();
        #pragma unroll
        for (int kk = 0; kk < 4; kk++) {
            int kbase = kk * 16;
            unsigned ah[2][4], al[2][4];
            #pragma unroll
            for (int ma = 0; ma < 2; ma++) {
                int rowq = warp_m * 32 + ma * 16 + aRowOff;
                unsigned ad = smem_u32(&sAh[rowq][kbase + aColOff]);
                asm volatile("ldmatrix.sync.aligned.m8n8.x4.shared.b16 {%0,%1,%2,%3}, [%4];"
                             : "=r"(ah[ma][0]), "=r"(ah[ma][1]), "=r"(ah[ma][2]), "=r"(ah[ma][3]) : "r"(ad));
                ad = smem_u32(&sAl[rowq][kbase + aColOff]);
                asm volatile("ldmatrix.sync.aligned.m8n8.x4.shared.b16 {%0,%1,%2,%3}, [%4];"
                             : "=r"(al[ma][0]), "=r"(al[ma][1]), "=r"(al[ma][2]), "=r"(al[ma][3]) : "r"(ad));
            }
            unsigned bh_[8][2], bl_[8][2];
            #pragma unroll
            for (int np = 0; np < 4; np++) {
                int rowk = warp_n * 64 + np * 16 + bRowOff;
                unsigned r0, r1, r2, r3;
                unsigned ad = smem_u32(&sBh[rowk][kbase + bColOff]);
                asm volatile("ldmatrix.sync.aligned.m8n8.x4.shared.b16 {%0,%1,%2,%3}, [%4];"
                             : "=r"(r0), "=r"(r1), "=r"(r2), "=r"(r3) : "r"(ad));
                bh_[np*2+0][0] = r0; bh_[np*2+0][1] = r1;
                bh_[np*2+1][0] = r2; bh_[np*2+1][1] = r3;
                ad = smem_u32(&sBl[rowk][kbase + bColOff]);
                asm volatile("ldmatrix.sync.aligned.m8n8.x4.shared.b16 {%0,%1,%2,%3}, [%4];"
                             : "=r"(r0), "=r"(r1), "=r"(r2), "=r"(r3) : "r"(ad));
                bl_[np*2+0][0] = r0; bl_[np*2+0][1] = r1;
                bl_[np*2+1][0] = r2; bl_[np*2+1][1] = r3;
            }
            #pragma unroll
            for (int ma = 0; ma < 2; ma++) {
                #pragma unroll
                for (int na = 0; na < 8; na++) {
                    asm volatile("mma.sync.aligned.m16n8k16.row.col.f32.f16.f16.f32 "
                        "{%0,%1,%2,%3}, {%4,%5,%6,%7}, {%8,%9}, {%0,%1,%2,%3};"
                        : "+f"(acc[ma][na][0]), "+f"(acc[ma][na][1]), "+f"(acc[ma][na][2]), "+f"(acc[ma][na][3])
                        : "r"(ah[ma][0]), "r"(ah[ma][1]), "r"(ah[ma][2]), "r"(ah[ma][3]),
                          "r"(bh_[na][0]), "r"(bh_[na][1]));
                    asm volatile("mma.sync.aligned.m16n8k16.row.col.f32.f16.f16.f32 "
                        "{%0,%1,%2,%3}, {%4,%5,%6,%7}, {%8,%9}, {%0,%1,%2,%3};"
                        : "+f"(acc[ma][na][0]), "+f"(acc[ma][na][1]), "+f"(acc[ma][na][2]), "+f"(acc[ma][na][3])
                        : "r"(ah[ma][0]), "r"(ah[ma][1]), "r"(ah[ma][2]), "r"(ah[ma][3]),
                          "r"(bl_[na][0]), "r"(bl_[na][1]));
                    asm volatile("mma.sync.aligned.m16n8k16.row.col.f32.f16.f16.f32 "
                        "{%0,%1,%2,%3}, {%4,%5,%6,%7}, {%8,%9}, {%0,%1,%2,%3};"
                        : "+f"(acc[ma][na][0]), "+f"(acc[ma][na][1]), "+f"(acc[ma][na][2]), "+f"(acc[ma][na][3])
                        : "r"(al[ma][0]), "r"(al[ma][1]), "r"(al[ma][2]), "r"(al[ma][3]),
                          "r"(bh_[na][0]), "r"(bh_[na][1]));
                }
            }
        }
        __syncthreads();
    }

    // epilogue: bias + scatter
    int g = lane >> 2, tg = lane & 3;
    #pragma unroll
    for (int ma = 0; ma < 2; ma++) {
        #pragma unroll
        for (int half = 0; half < 2; half++) {
            int m = m0 + warp_m * 32 + ma * 16 + g + half * 8;
            int b = m >> 10, n = m & 1023;
            #pragma unroll
            for (int na = 0; na < 8; na++) {
                int c = c0 + warp_n * 64 + na * 8 + tg * 2;
                float2 v;
                v.x = acc[ma][na][half*2+0] + bias[c];
                v.y = acc[ma][na][half*2+1] + bias[c+1];
                int part = c >> 10;
                int hc = c & 1023;
                int h = hc >> 6, dh = hc & 63;
                size_t idx = ((size_t)((b * HH + h) * NN + n)) * DHd + dh;
                if (part == 2) {
                    __half2 hv = __floats2half2_rn(v.x, v.y);
                    *(unsigned*)&g_V16[idx] = *(unsigned*)&hv;
                } else {
                    __half h0, l0, h1, l1;
                    split16(v.x, h0, l0);
                    split16(v.y, h1, l1);
                    __half2 hp = __halves2half2(h0, h1);
                    __half2 lp = __halves2half2(l0, l1);
                    if (part == 0) {
                        *(float2*)&g_Q[idx] = v;
                        *(unsigned*)&g_Q16h[idx] = *(unsigned*)&hp;
                        *(unsigned*)&g_Q16l[idx] = *(unsigned*)&lp;
                    } else {
                        *(unsigned*)&g_K16h[idx] = *(unsigned*)&hp;
                        *(unsigned*)&g_K16l[idx] = *(unsigned*)&lp;
                    }
                }
            }
        }
    }
}

// =====================================================================
// Kernel 2: QR[row][t] = Q[row] . rel_k_emb[t]  (fp32, smem-staged)
// =====================================================================
__global__ __launch_bounds__(256) void k_qr(const float* __restrict__ relk) {
    __shared__ float sQ[32][68];
    __shared__ float srk[64][132];
    int tid = threadIdx.x;
    int row0 = blockIdx.x * 32;
    for (int e = tid; e < 32 * 64; e += 256) {
        int r = e >> 6, d = e & 63;
        sQ[r][d] = g_Q[(size_t)(row0 + r) * DHd + d];
    }
    for (int e = tid; e < 64 * 132; e += 256) {
        int d = e / 132, t = e % 132;
        srk[d][t] = (t < VOC) ? relk[t * DHd + d] : 0.f;
    }
    __syncthreads();
    for (int g = tid; g < 32 * 33; g += 256) {
        int r = g / 33, tt = g % 33;
        u64 a01 = 0, a23 = 0;
        #pragma unroll 16
        for (int d = 0; d < 64; d++) {
            u64 qd = dup2(sQ[r][d]);
            ulonglong2 f = *(const ulonglong2*)&srk[d][tt * 4];
            ffma2(a01, qd, f.x);
            ffma2(a23, qd, f.y);
        }
        float2 lo = unpack2(a01), hi = unpack2(a23);
        size_t base = (size_t)(row0 + r) * VOC;
        int t0 = tt * 4;
        if (tt < 32) {
            g_QR[base + t0 + 0] = lo.x;
            g_QR[base + t0 + 1] = lo.y;
            g_QR[base + t0 + 2] = hi.x;
            g_QR[base + t0 + 3] = hi.y;
        } else {
            g_QR[base + 128] = lo.x;
        }
    }
}

// =====================================================================
// Kernel 3: S = SCALE*(Q.K^T) + QR gather via split-fp16 MMA.
// grid (8, 8, 64), 256 threads, 2 CTAs/SM, cp.async staging.
// =====================================================================
__global__ __launch_bounds__(256, 2) void k_scores() {
    extern __shared__ __half sdyn[];
    __half (*sQh)[72] = (__half(*)[72])(sdyn);
    __half (*sQl)[72] = (__half(*)[72])(sdyn + 128 * 72);
    __half (*sKh)[72] = (__half(*)[72])(sdyn + 2 * 128 * 72);
    __half (*sKl)[72] = (__half(*)[72])(sdyn + 3 * 128 * 72);
    int tid = threadIdx.x;
    int lane = tid & 31, wid = tid >> 5;
    int warp_m = wid & 3;
    int warp_n = wid >> 2;
    int bh = blockIdx.z;
    int i0 = blockIdx.y * 128, j0 = blockIdx.x * 128;

    {
        const __half* gqh = g_Q16h + (size_t)(bh * NN + i0) * DHd;
        const __half* gql = g_Q16l + (size_t)(bh * NN + i0) * DHd;
        const __half* gkh = g_K16h + (size_t)(bh * NN + j0) * DHd;
        const __half* gkl = g_K16l + (size_t)(bh * NN + j0) * DHd;
        for (int e = tid; e < 1024; e += 256) {
            int r = e >> 3, s = (e & 7) * 8;
            cp16(smem_u32(&sQh[r][s]), &gqh[r * DHd + s]);
            cp16(smem_u32(&sQl[r][s]), &gql[r * DHd + s]);
            cp16(smem_u32(&sKh[r][s]), &gkh[r * DHd + s]);
            cp16(smem_u32(&sKl[r][s]), &gkl[r * DHd + s]);
        }
        cp_commit_wait();
    }
    __syncthreads();

    float acc[2][8][4];
    #pragma unroll
    for (int ma = 0; ma < 2; ma++)
        #pragma unroll
        for (int na = 0; na < 8; na++)
            #pragma unroll
            for (int q = 0; q < 4; q++) acc[ma][na][q] = 0.f;

    int lm = lane >> 3;
    int lr = lane & 7;
    int aRowOff = (lm & 1) * 8 + lr;
    int aColOff = (lm >> 1) * 8;
    int bRowOff = (lm >> 1) * 8 + lr;
    int bColOff = (lm & 1) * 8;

    #pragma unroll
    for (int kk = 0; kk < 4; kk++) {
        int kbase = kk * 16;
        unsigned ah[2][4], al[2][4];
        #pragma unroll
        for (int ma = 0; ma < 2; ma++) {
            int rowq = warp_m * 32 + ma * 16 + aRowOff;
            unsigned addrh = smem_u32(&sQh[rowq][kbase + aColOff]);
            asm volatile("ldmatrix.sync.aligned.m8n8.x4.shared.b16 {%0,%1,%2,%3}, [%4];"
                         : "=r"(ah[ma][0]), "=r"(ah[ma][1]), "=r"(ah[ma][2]), "=r"(ah[ma][3])
                         : "r"(addrh));
            unsigned addrl = smem_u32(&sQl[rowq][kbase + aColOff]);
            asm volatile("ldmatrix.sync.aligned.m8n8.x4.shared.b16 {%0,%1,%2,%3}, [%4];"
                         : "=r"(al[ma][0]), "=r"(al[ma][1]), "=r"(al[ma][2]), "=r"(al[ma][3])
                         : "r"(addrl));
        }
        unsigned bh_[8][2], bl_[8][2];
        #pragma unroll
        for (int np = 0; np < 4; np++) {
            int rowk = warp_n * 64 + np * 16 + bRowOff;
            unsigned r0, r1, r2, r3;
            unsigned addrh = smem_u32(&sKh[rowk][kbase + bColOff]);
            asm volatile("ldmatrix.sync.aligned.m8n8.x4.shared.b16 {%0,%1,%2,%3}, [%4];"
                         : "=r"(r0), "=r"(r1), "=r"(r2), "=r"(r3) : "r"(addrh));
            bh_[np*2+0][0] = r0; bh_[np*2+0][1] = r1;
            bh_[np*2+1][0] = r2; bh_[np*2+1][1] = r3;
            unsigned addrl = smem_u32(&sKl[rowk][kbase + bColOff]);
            asm volatile("ldmatrix.sync.aligned.m8n8.x4.shared.b16 {%0,%1,%2,%3}, [%4];"
                         : "=r"(r0), "=r"(r1), "=r"(r2), "=r"(r3) : "r"(addrl));
            bl_[np*2+0][0] = r0; bl_[np*2+0][1] = r1;
            bl_[np*2+1][0] = r2; bl_[np*2+1][1] = r3;
        }
        #pragma unroll
        for (int ma = 0; ma < 2; ma++) {
            #pragma unroll
            for (int na = 0; na < 8; na++) {
                asm volatile("mma.sync.aligned.m16n8k16.row.col.f32.f16.f16.f32 "
                    "{%0,%1,%2,%3}, {%4,%5,%6,%7}, {%8,%9}, {%0,%1,%2,%3};"
                    : "+f"(acc[ma][na][0]), "+f"(acc[ma][na][1]), "+f"(acc[ma][na][2]), "+f"(acc[ma][na][3])
                    : "r"(ah[ma][0]), "r"(ah[ma][1]), "r"(ah[ma][2]), "r"(ah[ma][3]),
                      "r"(bh_[na][0]), "r"(bh_[na][1]));
                asm volatile("mma.sync.aligned.m16n8k16.row.col.f32.f16.f16.f32 "
                    "{%0,%1,%2,%3}, {%4,%5,%6,%7}, {%8,%9}, {%0,%1,%2,%3};"
                    : "+f"(acc[ma][na][0]), "+f"(acc[ma][na][1]), "+f"(acc[ma][na][2]), "+f"(acc[ma][na][3])
                    : "r"(ah[ma][0]), "r"(ah[ma][1]), "r"(ah[ma][2]), "r"(ah[ma][3]),
                      "r"(bl_[na][0]), "r"(bl_[na][1]));
                asm volatile("mma.sync.aligned.m16n8k16.row.col.f32.f16.f16.f32 "
                    "{%0,%1,%2,%3}, {%4,%5,%6,%7}, {%8,%9}, {%0,%1,%2,%3};"
                    : "+f"(acc[ma][na][0]), "+f"(acc[ma][na][1]), "+f"(acc[ma][na][2]), "+f"(acc[ma][na][3])
                    : "r"(al[ma][0]), "r"(al[ma][1]), "r"(al[ma][2]), "r"(al[ma][3]),
                      "r"(bh_[na][0]), "r"(bh_[na][1]));
            }
        }
    }

    int g = lane >> 2, tg = lane & 3;
    #pragma unroll
    for (int ma = 0; ma < 2; ma++) {
        int rowA = i0 + warp_m * 32 + ma * 16 + g;
        #pragma unroll
        for (int half = 0; half < 2; half++) {
            int ii = rowA + half * 8;
            const float* qr = &g_QR[(size_t)(bh * NN + ii) * VOC];
            size_t sbase = ((size_t)(bh * NN + ii)) * NN;
            #pragma unroll
            for (int na = 0; na < 8; na++) {
                int jj = j0 + warp_n * 64 + na * 8 + tg * 2;
                int d0 = ii - jj;
                d0 = d0 < -MAXREL ? -MAXREL : (d0 > MAXREL ? MAXREL : d0);
                int d1 = ii - (jj + 1);
                d1 = d1 < -MAXREL ? -MAXREL : (d1 > MAXREL ? MAXREL : d1);
                float2 v;
                v.x = acc[ma][na][half*2+0] * SCALEv + qr[d0 + MAXREL];
                v.y = acc[ma][na][half*2+1] * SCALEv + qr[d1 + MAXREL];
                *(float2*)&g_S[sbase + jj] = v;
            }
        }
    }
}

// float -> order-preserving uint key
__device__ __forceinline__ unsigned ftokey(float f) {
    unsigned u = __float_as_uint(f);
    return (u & 0x80000000u) ? ~u : (u | 0x80000000u);
}

// =====================================================================
// Kernel 4 (fused): radix-select + masked softmax + compaction + ARel.
// Parallel ARel (4 t-chunks x 64 dims, all 256 threads).
// One block (256 threads) per score row.
// =====================================================================
__global__ __launch_bounds__(256) void k_select(const float* __restrict__ relv) {
    __shared__ float sbuf[1024];
    __shared__ int   hist[256];
    __shared__ float wredf[8];
    __shared__ float wredf2[8];
    __shared__ int   wredi[8];
    __shared__ float rbin[VOC];
    __shared__ float sred[4][64];
    __shared__ unsigned sh_selb;
    __shared__ int      sh_rem;

    int row = blockIdx.x;
    int tid = threadIdx.x;
    int lane = tid & 31, wid = tid >> 5;
    int i = row & (NN - 1);
    const float* src = &g_S[(size_t)row * NN];

    float4 lv4 = *(const float4*)&src[tid * 4];
    float lv[4] = {lv4.x, lv4.y, lv4.z, lv4.w};
    unsigned kv[4];
    #pragma unroll
    for (int r = 0; r < 4; r++) kv[r] = ftokey(lv[r]);

    float m = fmaxf(fmaxf(lv[0], lv[1]), fmaxf(lv[2], lv[3]));
    #pragma unroll
    for (int off = 16; off > 0; off >>= 1)
        m = fmaxf(m, __shfl_xor_sync(0xffffffffu, m, off));
    if (lane == 0) wredf[wid] = m;
    __syncthreads();
    float rmax = wredf[0];
    #pragma unroll
    for (int w = 1; w < 8; w++) rmax = fmaxf(rmax, wredf[w]);

    unsigned prefix = 0;
    int need = TOPKv;
    for (int round = 3; round >= 0; round--) {
        hist[tid] = 0;
        __syncthreads();
        unsigned mask = (round == 3) ? 0u : (0xFFFFFFFFu << ((round + 1) * 8));
        #pragma unroll
        for (int r = 0; r < 4; r++) {
            if ((kv[r] & mask) == prefix)
                atomicAdd(&hist[(kv[r] >> (round * 8)) & 255], 1);
        }
        __syncthreads();
        int h = hist[tid];
        int s = h;
        #pragma unroll
        for (int off = 1; off < 32; off <<= 1) {
            int v = __shfl_down_sync(0xffffffffu, s, off);
            if (lane + off < 32) s += v;
        }
        int wtot = __shfl_sync(0xffffffffu, s, 0);
        if (lane == 0) wredi[wid] = wtot;
        __syncthreads();
        int tail = 0;
        #pragma unroll
        for (int w = 0; w < 8; w++) if (w > wid) tail += wredi[w];
        int Sb = s + tail;
        int Sb1 = Sb - h;
        if (Sb >= need && Sb1 < need) { sh_selb = (unsigned)tid; sh_rem = Sb1; }
        __syncthreads();
        prefix |= sh_selb << (round * 8);
        need -= sh_rem;
        __syncthreads();
    }
    unsigned thrkey = prefix;

    float lsum = 0.f;
    #pragma unroll
    for (int r = 0; r < 4; r++) {
        int j = tid * 4 + r;
        float e;
        if (kv[r] >= thrkey) { e = __expf(lv[r] - rmax); lsum += e; }
        else e = -1.0f;
        sbuf[j] = e;
    }
    float ws = lsum;
    #pragma unroll
    for (int off = 16; off > 0; off >>= 1)
        ws += __shfl_xor_sync(0xffffffffu, ws, off);
    if (lane == 0) wredf[wid] = ws;
    __syncthreads();
    float tot = 0.f;
    #pragma unroll
    for (int w = 0; w < 8; w++) tot += wredf[w];
    float inv = 1.0f / tot;

    if (tid >= 1 && tid < 128) {
        int j = i + MAXREL - tid;
        float v = 0.f;
        if (j >= 0 && j < NN) {
            float e = sbuf[j];
            if (e >= 0.f) v = e * inv;
        }
        rbin[tid] = v;
    }
    float s0 = 0.f, s128 = 0.f;
    #pragma unroll
    for (int r = 0; r < 4; r++) {
        int j = tid * 4 + r;
        float e = sbuf[j];
        float a = (e >= 0.f) ? e * inv : 0.f;
        if (j >= i + MAXREL) s0 += a;
        if (j <= i - MAXREL) s128 += a;
    }
    #pragma unroll
    for (int off = 16; off > 0; off >>= 1) {
        s0   += __shfl_xor_sync(0xffffffffu, s0, off);
        s128 += __shfl_xor_sync(0xffffffffu, s128, off);
    }
    __syncthreads();
    if (lane == 0) { wredf[wid] = s0; wredf2[wid] = s128; }
    __syncthreads();
    if (tid == 0) {
        float a = 0.f, b = 0.f;
        #pragma unroll
        for (int w = 0; w < 8; w++) { a += wredf[w]; b += wredf2[w]; }
        rbin[0] = a; rbin[MAXREL * 2] = b;
    }
    __syncthreads();

    // ---- ARel = rbin . rel_v  (all 256 threads: 4 t-chunks x 64 dims) ----
    {
        int dd = tid & 63, part = tid >> 6;
        int t0 = part * 32;
        int tn = (part == 3) ? 33 : 32;
        float acc = 0.f;
        for (int t = t0; t < t0 + tn; t++)
            acc += rbin[t] * __ldg(&relv[t * DHd + dd]);
        sred[part][dd] = acc;
    }
    __syncthreads();
    if (tid < DHd) {
        float a = (sred[0][tid] + sred[1][tid]) + (sred[2][tid] + sred[3][tid]);
        g_ARel[(size_t)row * DHd + tid] = a;
    }

    int kc = 0;
    #pragma unroll
    for (int r = 0; r < 4; r++) if (sbuf[tid * 4 + r] >= 0.f) kc++;
    int p = kc;
    #pragma unroll
    for (int off = 1; off < 32; off <<= 1) {
        int v = __shfl_up_sync(0xffffffffu, p, off);
        if (lane >= off) p += v;
    }
    if (lane == 31) wredi[wid] = p;
    __syncthreads();
    int base = 0;
    #pragma unroll
    for (int w = 0; w < 8; w++) if (w < wid) base += wredi[w];
    int pos = base + p - kc;
    size_t cbase = (size_t)row * TOPKv;
    #pragma unroll
    for (int r = 0; r < 4; r++) {
        int j = tid * 4 + r;
        float e = sbuf[j];
        if (e >= 0.f) {
            if (pos < TOPKv) { g_CI[cbase + pos] = j; g_CW[cbase + pos] = e * inv; }
            pos++;
        }
    }
}

// =====================================================================
// Kernel 5: sparse apply with fp16 V (proven). ord==2 additionally emits
// Res in FLAT [m][dim] layout as fp16 hi/lo for the MMA out-GEMM.
// grid (bh, row-half) = 128 blocks, 512 threads.
// =====================================================================
__global__ __launch_bounds__(512) void k_apply(int ord, const float* __restrict__ alphas_raw) {
    extern __shared__ char smemc[];
    unsigned* sVu = (unsigned*)smemc;
    float2*   sIW = (float2*)(smemc + 1024 * 32 * 4);

    const __half* Vin16  = (ord == 0) ? g_V16  : ((ord == 1) ? g_VA16 : g_VB16);
    __half*       Vout16 = (ord == 0) ? g_VA16 : ((ord == 1) ? g_VB16 : g_VA16);

    int bh = blockIdx.x >> 1;
    int rh = blockIdx.x & 1;
    int tid = threadIdx.x, wid = tid >> 5, lane = tid & 31;

    {
        const uint4* srcv = (const uint4*)(Vin16 + (size_t)bh * NN * DHd);
        uint4* dstv = (uint4*)sVu;
        for (int e = tid; e < 8192; e += 512) dstv[e] = srcv[e];
    }
    __syncthreads();

    int h = bh & (HH - 1);
    int bb = bh >> 4;
    float araw = alphas_raw[ord * HH + h];
    float alpha = 1.0f / (1.0f + __expf(-araw));
    float2* myIW = sIW + wid * 256;

    for (int i = rh * 512 + wid; i < rh * 512 + 512; i += 16) {
        int row = bh * NN + i;
        const int*   ci = &g_CI[(size_t)row * TOPKv];
        const float* cw = &g_CW[(size_t)row * TOPKv];
        #pragma unroll
        for (int q = 0; q < 8; q++) {
            int p = q * 32 + lane;
            myIW[p] = make_float2(cw[p], __int_as_float(ci[p]));
        }
        __syncwarp();
        float2 a0 = {0.f, 0.f}, a1 = {0.f, 0.f}, a2 = {0.f, 0.f}, a3 = {0.f, 0.f};
        #pragma unroll 4
        for (int p = 0; p < TOPKv; p += 4) {
            float2 w0 = myIW[p+0], w1 = myIW[p+1], w2 = myIW[p+2], w3 = myIW[p+3];
            unsigned u0 = sVu[__float_as_int(w0.y) * 32 + lane];
            unsigned u1 = sVu[__float_as_int(w1.y) * 32 + lane];
            unsigned u2 = sVu[__float_as_int(w2.y) * 32 + lane];
            unsigned u3 = sVu[__float_as_int(w3.y) * 32 + lane];
            float2 v0 = __half22float2(*(__half2*)&u0);
            float2 v1 = __half22float2(*(__half2*)&u1);
            float2 v2 = __half22float2(*(__half2*)&u2);
            float2 v3 = __half22float2(*(__half2*)&u3);
            a0.x += w0.x * v0.x; a0.y += w0.x * v0.y;
            a1.x += w1.x * v1.x; a1.y += w1.x * v1.y;
            a2.x += w2.x * v2.x; a2.y += w2.x * v2.y;
            a3.x += w3.x * v3.x; a3.y += w3.x * v3.y;
        }
        float2 acc;
        acc.x = (a0.x + a1.x) + (a2.x + a3.x);
        acc.y = (a0.y + a1.y) + (a2.y + a3.y);
        __syncwarp();

        size_t oidx = (size_t)row * DHd + 2 * lane;
        if (ord == 0) {
            float2 ar = *(const float2*)&g_ARel[oidx];
            acc.x += ar.x; acc.y += ar.y;
        }
        __half2 hv = __floats2half2_rn(acc.x, acc.y);
        *(unsigned*)&Vout16[oidx] = *(unsigned*)&hv;
        if (ord == 0) {
            float2 rv = make_float2(alpha * acc.x, alpha * acc.y);
            *(float2*)&g_Res[oidx] = rv;
        } else if (ord == 1) {
            float2 pr = *(float2*)&g_Res[oidx];
            pr.x += alpha * acc.x;
            pr.y += alpha * acc.y;
            *(float2*)&g_Res[oidx] = pr;
        } else {
            float2 pr = *(float2*)&g_Res[oidx];
            pr.x += alpha * acc.x;
            pr.y += alpha * acc.y;
            size_t fidx = ((size_t)(bb * 1024 + i)) * DIMV + h * DHd + 2 * lane;
            __half h0, l0, h1, l1;
            split16(pr.x, h0, l0);
            split16(pr.y, h1, l1);
            __half2 hp = __halves2half2(h0, h1);
            __half2 lp = __halves2half2(l0, l1);
            *(unsigned*)&g_R16h[fidx] = *(unsigned*)&hp;
            *(unsigned*)&g_R16l[fidx] = *(unsigned*)&lp;
        }
    }
}

// =====================================================================
// Kernel 6: out = Res_flat @ Wout^T + bout via split-fp16 MMA, 2 CTAs/SM,
// cp.async staging. grid (8, 32), 256 threads.
// =====================================================================
__global__ __launch_bounds__(256, 2) void k_gemm_out(const float* __restrict__ bias,
                                                     float* __restrict__ out) {
    extern __shared__ __half sdyn[];
    __half (*sAh)[72] = (__half(*)[72])(sdyn);
    __half (*sAl)[72] = (__half(*)[72])(sdyn + 128 * 72);
    __half (*sBh)[72] = (__half(*)[72])(sdyn + 2 * 128 * 72);
    __half (*sBl)[72] = (__half(*)[72])(sdyn + 3 * 128 * 72);
    int tid = threadIdx.x;
    int lane = tid & 31, wid = tid >> 5;
    int warp_m = wid & 3, warp_n = wid >> 2;
    int m0 = blockIdx.y * 128, o0 = blockIdx.x * 128;

    float acc[2][8][4];
    #pragma unroll
    for (int ma = 0; ma < 2; ma++)
        #pragma unroll
        for (int na = 0; na < 8; na++)
            #pragma unroll
            for (int q = 0; q < 4; q++) acc[ma][na][q] = 0.f;

    int lm = lane >> 3, lr = lane & 7;
    int aRowOff = (lm & 1) * 8 + lr;
    int aColOff = (lm >> 1) * 8;
    int bRowOff = (lm >> 1) * 8 + lr;
    int bColOff = (lm & 1) * 8;

    for (int kc = 0; kc < DIMV; kc += 64) {
        for (int e = tid; e < 1024; e += 256) {
            int r = e >> 3, s = (e & 7) * 8;
            cp16(smem_u32(&sAh[r][s]), &g_R16h[(size_t)(m0 + r) * DIMV + kc + s]);
            cp16(smem_u32(&sAl[r][s]), &g_R16l[(size_t)(m0 + r) * DIMV + kc + s]);
            cp16(smem_u32(&sBh[r][s]), &g_Wo16h[(size_t)(o0 + r) * DIMV + kc + s]);
            cp16(smem_u32(&sBl[r][s]), &g_Wo16l[(size_t)(o0 + r) * DIMV + kc + s]);
        }
        cp_commit_wait();
        __syncthreads();
        #pragma unroll
        for (int kk = 0; kk < 4; kk++) {
            int kbase = kk * 16;
            unsigned ah[2][4], al[2][4];
            #pragma unroll
            for (int ma = 0; ma < 2; ma++) {
                int rowq = warp_m * 32 + ma * 16 + aRowOff;
                unsigned ad = smem_u32(&sAh[rowq][kbase + aColOff]);
                asm volatile("ldmatrix.sync.aligned.m8n8.x4.shared.b16 {%0,%1,%2,%3}, [%4];"
                             : "=r"(ah[ma][0]), "=r"(ah[ma][1]), "=r"(ah[ma][2]), "=r"(ah[ma][3]) : "r"(ad));
                ad = smem_u32(&sAl[rowq][kbase + aColOff]);
                asm volatile("ldmatrix.sync.aligned.m8n8.x4.shared.b16 {%0,%1,%2,%3}, [%4];"
                             : "=r"(al[ma][0]), "=r"(al[ma][1]), "=r"(al[ma][2]), "=r"(al[ma][3]) : "r"(ad));
            }
            unsigned bh_[8][2], bl_[8][2];
            #pragma unroll
            for (int np = 0; np < 4; np++) {
                int rowk = warp_n * 64 + np * 16 + bRowOff;
                unsigned r0, r1, r2, r3;
                unsigned ad = smem_u32(&sBh[rowk][kbase + bColOff]);
                asm volatile("ldmatrix.sync.aligned.m8n8.x4.shared.b16 {%0,%1,%2,%3}, [%4];"
                             : "=r"(r0), "=r"(r1), "=r"(r2), "=r"(r3) : "r"(ad));
                bh_[np*2+0][0] = r0; bh_[np*2+0][1] = r1;
                bh_[np*2+1][0] = r2; bh_[np*2+1][1] = r3;
                ad = smem_u32(&sBl[rowk][kbase + bColOff]);
                asm volatile("ldmatrix.sync.aligned.m8n8.x4.shared.b16 {%0,%1,%2,%3}, [%4];"
                             : "=r"(r0), "=r"(r1), "=r"(r2), "=r"(r3) : "r"(ad));
                bl_[np*2+0][0] = r0; bl_[np*2+0][1] = r1;
                bl_[np*2+1][0] = r2; bl_[np*2+1][1] = r3;
            }
            #pragma unroll
            for (int ma = 0; ma < 2; ma++) {
                #pragma unroll
                for (int na = 0; na < 8; na++) {
                    asm volatile("mma.sync.aligned.m16n8k16.row.col.f32.f16.f16.f32 "
                        "{%0,%1,%2,%3}, {%4,%5,%6,%7}, {%8,%9}, {%0,%1,%2,%3};"
                        : "+f"(acc[ma][na][0]), "+f"(acc[ma][na][1]), "+f"(acc[ma][na][2]), "+f"(acc[ma][na][3])
                        : "r"(ah[ma][0]), "r"(ah[ma][1]), "r"(ah[ma][2]), "r"(ah[ma][3]),
                          "r"(bh_[na][0]), "r"(bh_[na][1]));
                    asm volatile("mma.sync.aligned.m16n8k16.row.col.f32.f16.f16.f32 "
                        "{%0,%1,%2,%3}, {%4,%5,%6,%7}, {%8,%9}, {%0,%1,%2,%3};"
                        : "+f"(acc[ma][na][0]), "+f"(acc[ma][na][1]), "+f"(acc[ma][na][2]), "+f"(acc[ma][na][3])
                        : "r"(ah[ma][0]), "r"(ah[ma][1]), "r"(ah[ma][2]), "r"(ah[ma][3]),
                          "r"(bl_[na][0]), "r"(bl_[na][1]));
                    asm volatile("mma.sync.aligned.m16n8k16.row.col.f32.f16.f16.f32 "
                        "{%0,%1,%2,%3}, {%4,%5,%6,%7}, {%8,%9}, {%0,%1,%2,%3};"
                        : "+f"(acc[ma][na][0]), "+f"(acc[ma][na][1]), "+f"(acc[ma][na][2]), "+f"(acc[ma][na][3])
                        : "r"(al[ma][0]), "r"(al[ma][1]), "r"(al[ma][2]), "r"(al[ma][3]),
                          "r"(bh_[na][0]), "r"(bh_[na][1]));
                }
            }
        }
        __syncthreads();
    }

    int g = lane >> 2, tg = lane & 3;
    #pragma unroll
    for (int ma = 0; ma < 2; ma++) {
        #pragma unroll
        for (int half = 0; half < 2; half++) {
            int m = m0 + warp_m * 32 + ma * 16 + g + half * 8;
            #pragma unroll
            for (int na = 0; na < 8; na++) {
                int o = o0 + warp_n * 64 + na * 8 + tg * 2;
                float2 v;
                v.x = acc[ma][na][half*2+0] + bias[o];
                v.y = acc[ma][na][half*2+1] + bias[o+1];
                *(float2*)&out[(size_t)m * DIMV + o] = v;
            }
        }
    }
}

// =====================================================================
extern "C" void kernel_launch(void* const* d_in, const int* in_sizes, int n_in,
                              void* d_out, int out_size) {
    const float* x      = (const float*)d_in[0];
    const float* Wqkv   = (const float*)d_in[1];
    const float* bqkv   = (const float*)d_in[2];
    const float* Wout   = (const float*)d_in[3];
    const float* bout   = (const float*)d_in[4];
    const float* relk   = (const float*)d_in[5];
    const float* relv   = (const float*)d_in[6];
    const float* alphas = (const float*)d_in[7];
    float* out = (float*)d_out;

    __half *xh, *xl, *wqh, *wql, *woh, *wol;
    cudaGetSymbolAddress((void**)&xh,  g_X16h);  cudaGetSymbolAddress((void**)&xl,  g_X16l);
    cudaGetSymbolAddress((void**)&wqh, g_Wq16h); cudaGetSymbolAddress((void**)&wql, g_Wq16l);
    cudaGetSymbolAddress((void**)&woh, g_Wo16h); cudaGetSymbolAddress((void**)&wol, g_Wo16l);

    k_split<<<(MQ * DIMV / 4 + 255) / 256, 256>>>(x, xh, xl, MQ * DIMV / 4);
    k_split<<<(CQKV * DIMV / 4 + 255) / 256, 256>>>(Wqkv, wqh, wql, CQKV * DIMV / 4);
    k_split<<<(DIMV * DIMV / 4 + 255) / 256, 256>>>(Wout, woh, wol, DIMV * DIMV / 4);

    cudaFuncSetAttribute(k_gemm_qkv, cudaFuncAttributeMaxDynamicSharedMemorySize, 4 * 128 * 72 * 2);
    k_gemm_qkv<<<dim3(24, 32), 256, 4 * 128 * 72 * 2>>>(bqkv);

    k_qr<<<ROWS / 32, 256>>>(relk);

    cudaFuncSetAttribute(k_scores, cudaFuncAttributeMaxDynamicSharedMemorySize, 4 * 128 * 72 * 2);
    k_scores<<<dim3(8, 8, BHH), 256, 4 * 128 * 72 * 2>>>();

    k_select<<<ROWS, 256>>>(relv);

    cudaFuncSetAttribute(k_apply, cudaFuncAttributeMaxDynamicSharedMemorySize, 163840);
    k_apply<<<BHH * 2, 512, 163840>>>(0, alphas);
    k_apply<<<BHH * 2, 512, 163840>>>(1, alphas);
    k_apply<<<BHH * 2, 512, 163840>>>(2, alphas);

    cudaFuncSetAttribute(k_gemm_out, cudaFuncAttributeMaxDynamicSharedMemorySize, 4 * 128 * 72 * 2);
    k_gemm_out<<<dim3(8, 32), 256, 4 * 128 * 72 * 2>>>(bout, out);
}